// round 11
// baseline (speedup 1.0000x reference)
#include <cuda_runtime.h>
#include <cuda_bf16.h>
#include <math.h>
#include <stdint.h>

#define B_  8
#define CIN 64
#define H_  128
#define W_  128
#define HO  64
#define WO  128
#define CO  64
#define HW_ (H_*W_)

// Scratch (no allocations allowed -> __device__ globals)
__device__ float g_bias[32];
__device__ __align__(16) char g_Wsplit[9*16384];   // deform W: per tap hi 8KB + lo 8KB, SW128
__device__ __align__(16) char g_WomSplit[9*8192];  // conv W: per tap hi 4KB + lo 4KB, SW128
__device__ __align__(16) float g_xT[(size_t)B_*H_*W_*CIN];  // NHWC transpose of x (32MB)

__device__ __forceinline__ uint32_t smem_u32(const void* p) {
    uint32_t a;
    asm("{ .reg .u64 t; cvta.to.shared.u64 t, %1; cvt.u32.u64 %0, t; }" : "=r"(a) : "l"(p));
    return a;
}
__device__ __forceinline__ uint32_t sw128(uint32_t off) { return off ^ ((off >> 3) & 0x70); }

#define LDMATRIX_X4(r0,r1,r2,r3,addr) \
    asm volatile("ldmatrix.sync.aligned.m8n8.x4.shared.b16 {%0,%1,%2,%3}, [%4];" \
                 : "=r"(r0),"=r"(r1),"=r"(r2),"=r"(r3) : "r"(addr))
#define LDMATRIX_X2(r0,r1,addr) \
    asm volatile("ldmatrix.sync.aligned.m8n8.x2.shared.b16 {%0,%1}, [%2];" \
                 : "=r"(r0),"=r"(r1) : "r"(addr))

#define MMA_BF16(c, a0,a1,a2,a3, b0,b1) \
    asm volatile("mma.sync.aligned.m16n8k16.row.col.f32.bf16.bf16.f32 " \
                 "{%0,%1,%2,%3},{%4,%5,%6,%7},{%8,%9},{%0,%1,%2,%3};" \
                 : "+f"((c)[0]),"+f"((c)[1]),"+f"((c)[2]),"+f"((c)[3]) \
                 : "r"(a0),"r"(a1),"r"(a2),"r"(a3), "r"(b0),"r"(b1))

#define CP16(dst, src) \
    asm volatile("cp.async.cg.shared.global [%0], [%1], 16;" :: "r"(dst), "l"(src) : "memory")
#define CP_COMMIT() asm volatile("cp.async.commit_group;" ::: "memory")
#define CP_WAIT(n)  asm volatile("cp.async.wait_group %0;" :: "n"(n) : "memory")

// bf16 hi/lo split of (v0, v1) -> packed hi word + packed lo word
#define SPLIT2(v0, v1, h, lw) do { \
    asm("cvt.rn.bf16x2.f32 %0, %1, %2;" : "=r"(h) : "f"(v1), "f"(v0)); \
    float _h0 = __uint_as_float((h) << 16); \
    float _h1 = __uint_as_float((h) & 0xffff0000u); \
    float _l0 = (v0) - _h0, _l1 = (v1) - _h1; \
    asm("cvt.rn.bf16x2.f32 %0, %1, %2;" : "=r"(lw) : "f"(_l1), "f"(_l0)); \
} while (0)

// ---------------------------------------------------------------------------
// Kernel 0: weight repack (hi/lo split, SW128 swizzled)
// ---------------------------------------------------------------------------
__global__ void prep_kernel(const float* __restrict__ w_off, const float* __restrict__ b_off,
                            const float* __restrict__ w_mask, const float* __restrict__ b_mask,
                            const float* __restrict__ w_conv) {
    int idx = blockIdx.x * blockDim.x + threadIdx.x;
    if (idx < 9*64*64) {
        int k = idx / 4096; int r = idx & 4095; int o = r >> 6; int c = r & 63;
        float w = w_conv[(o*64 + c)*9 + k];
        __nv_bfloat16 hi = __float2bfloat16(w);
        __nv_bfloat16 lo = __float2bfloat16(w - __bfloat162float(hi));
        uint32_t sw = sw128((uint32_t)(o*128 + c*2));
        *(__nv_bfloat16*)(g_Wsplit + k*16384 + sw)        = hi;
        *(__nv_bfloat16*)(g_Wsplit + k*16384 + 8192 + sw) = lo;
    }
    if (idx < 9*32*64) {
        int k = idx / 2048; int r = idx & 2047; int o = r >> 6; int c = r & 63;
        float w = 0.f;
        if (o < 18)       w = w_off[(o*64 + c)*9 + k];
        else if (o < 27)  w = w_mask[((o-18)*64 + c)*9 + k];
        __nv_bfloat16 hi = __float2bfloat16(w);
        __nv_bfloat16 lo = __float2bfloat16(w - __bfloat162float(hi));
        uint32_t sw = sw128((uint32_t)(o*128 + c*2));
        *(__nv_bfloat16*)(g_WomSplit + k*8192 + sw)        = hi;
        *(__nv_bfloat16*)(g_WomSplit + k*8192 + 4096 + sw) = lo;
    }
    if (idx < 32) {
        float v = 0.f;
        if (idx < 18)      v = b_off[idx];
        else if (idx < 27) v = b_mask[idx - 18];
        g_bias[idx] = v;
    }
}

// ---------------------------------------------------------------------------
// Kernel 0b: NCHW -> NHWC transpose of x
// ---------------------------------------------------------------------------
__global__ void __launch_bounds__(256) transpose_kernel(const float* __restrict__ x) {
    __shared__ float t[64][33];
    int x0 = blockIdx.x * 32, y = blockIdx.y, b = blockIdx.z;
    int tx = threadIdx.x & 31, tc = threadIdx.x >> 5;
    const float* xb = x + (size_t)b * CIN * HW_ + y*W_ + x0;
    #pragma unroll
    for (int cc = 0; cc < 8; ++cc)
        t[tc + cc*8][tx] = __ldg(xb + (size_t)(tc + cc*8)*HW_ + tx);
    __syncthreads();
    float* dst = g_xT + ((size_t)b*HW_ + y*W_ + x0) * CIN;
    int c = threadIdx.x & 63, xx = threadIdx.x >> 6;
    #pragma unroll
    for (int q = 0; q < 8; ++q)
        dst[(size_t)(xx + q*4)*CIN + c] = t[c][xx + q*4];
}

// ---------------------------------------------------------------------------
// Fused kernel: 128px x 64o tile, single-buffered W, 3 CTAs/SM target.
// ---------------------------------------------------------------------------
#define SM_A     0          // A: hi 16KB [0,16384), lo [16384,32768)
#define SM_W     32768      // W single buffer 16KB (ph1: hi@0/lo@4096; ph2: hi@0/lo@8192)
#define SM_META  49152      // meta double buffer: 2 x 128px x 32B = 8KB
#define SM_SOM   57344      // som[128 px][33 floats] = 16,896B
#define SM_TOTAL 74240      // -> 3 CTAs/SM (222,720 B)

__global__ void __launch_bounds__(256, 3) deform_kernel(const float* __restrict__ x,
                                                        float* __restrict__ out) {
    extern __shared__ char sm[];
    const uint32_t smb = smem_u32(sm);
    int tid = threadIdx.x;
    int l = tid & 31, w = tid >> 5;
    int ho = blockIdx.x, b = blockIdx.y;
    const float* xb = x + (size_t)b * CIN * HW_;

    int px0 = (w & 3) * 32;          // px tile base (gather + mma rows)
    int o0  = (w >> 2) * 32;         // phase-2 o tile base / gather channel half
    int oh  = (w >> 2) * 16;         // phase-1 o tile base

    // ---- ldmatrix lane offsets (per-ks, sw128 wraps full offset) ----
    uint32_t aoff[2][4], boff[2][4], b1off[4];
    {
        int arow = px0 + (l & 15);
        int acol = (l & 16) ? 16 : 0;
        #pragma unroll
        for (int m = 0; m < 2; ++m)
            #pragma unroll
            for (int ks = 0; ks < 4; ++ks)
                aoff[m][ks] = sw128((uint32_t)((arow + m*16)*128 + ks*32 + acol));
        int brow = o0 + (l & 7) + ((l & 16) ? 8 : 0);
        int bcol = (l & 8) ? 16 : 0;
        #pragma unroll
        for (int np = 0; np < 2; ++np)
            #pragma unroll
            for (int ks = 0; ks < 4; ++ks)
                boff[np][ks] = sw128((uint32_t)((brow + np*16)*128 + ks*32 + bcol));
        int b1row = oh + (l & 7) + ((l & 16) ? 8 : 0);
        #pragma unroll
        for (int ks = 0; ks < 4; ++ks)
            b1off[ks] = sw128((uint32_t)(b1row*128 + ks*32 + bcol));
    }

    int gpx = px0 + l;

    // ================= PHASE 1: offset/mask conv (128px x 32o) ================
    float acc1[2][2][4];
    #pragma unroll
    for (int m = 0; m < 2; ++m)
        #pragma unroll
        for (int nt = 0; nt < 2; ++nt)
            #pragma unroll
            for (int r = 0; r < 4; ++r) acc1[m][nt][r] = 0.f;

    #pragma unroll 1
    for (int k = 0; k < 9; ++k) {
        if (k) __syncthreads();      // GEMM(k-1) done -> A and W reusable

        // stage Wom(k) -> W (single buffer; latency hidden under A build)
        {
            uint32_t dst = smb + SM_W + tid*16;
            const char* src = g_WomSplit + k*8192 + tid*16;
            CP16(dst, src); CP16(dst + 4096u, src + 4096);
            CP_COMMIT();
        }
        // build A_k[px][c]: im2col row loads (NCHW coalesced)
        {
            int gy = 2*ho - 1 + (k/3);
            int gx = gpx - 1 + (k%3);
            bool vld = (gy >= 0) && (gx >= 0) && (gx < W_);
            char* ahi = sm + SM_A;
            char* alo = sm + SM_A + 16384;
            uint32_t rowoff = (uint32_t)(gpx*128 + o0*2);
            const float* xc = xb + (size_t)o0 * HW_ + gy*W_ + gx;
            #pragma unroll
            for (int j4 = 0; j4 < 4; ++j4) {
                uint32_t hv[4], lv[4];
                #pragma unroll
                for (int jj = 0; jj < 4; ++jj) {
                    float v0 = vld ? __ldg(xc)       : 0.f;
                    float v1 = vld ? __ldg(xc + HW_) : 0.f;
                    xc += 2*HW_;
                    SPLIT2(v0, v1, hv[jj], lv[jj]);
                }
                uint32_t sw = sw128(rowoff + j4*16);
                *(uint4*)(ahi + sw) = make_uint4(hv[0],hv[1],hv[2],hv[3]);
                *(uint4*)(alo + sw) = make_uint4(lv[0],lv[1],lv[2],lv[3]);
            }
        }
        CP_WAIT(0);
        __syncthreads();

        #pragma unroll
        for (int ks = 0; ks < 4; ++ks) {
            uint32_t ah[2][4], al[2][4], bh[4], bl[4];
            LDMATRIX_X4(ah[0][0],ah[0][1],ah[0][2],ah[0][3], smb + SM_A + aoff[0][ks]);
            LDMATRIX_X4(ah[1][0],ah[1][1],ah[1][2],ah[1][3], smb + SM_A + aoff[1][ks]);
            LDMATRIX_X4(al[0][0],al[0][1],al[0][2],al[0][3], smb + SM_A + 16384u + aoff[0][ks]);
            LDMATRIX_X4(al[1][0],al[1][1],al[1][2],al[1][3], smb + SM_A + 16384u + aoff[1][ks]);
            LDMATRIX_X4(bh[0],bh[1],bh[2],bh[3], smb + SM_W + b1off[ks]);
            LDMATRIX_X4(bl[0],bl[1],bl[2],bl[3], smb + SM_W + 4096u + b1off[ks]);
            #pragma unroll
            for (int m = 0; m < 2; ++m)
                #pragma unroll
                for (int nt = 0; nt < 2; ++nt) {
                    MMA_BF16(acc1[m][nt], ah[m][0],ah[m][1],ah[m][2],ah[m][3], bh[nt*2], bh[nt*2+1]);
                    MMA_BF16(acc1[m][nt], al[m][0],al[m][1],al[m][2],al[m][3], bh[nt*2], bh[nt*2+1]);
                    MMA_BF16(acc1[m][nt], ah[m][0],ah[m][1],ah[m][2],ah[m][3], bl[nt*2], bl[nt*2+1]);
                }
        }
    }

    // write som[px][o] = acc + bias (pitch 33)
    {
        float* som = (float*)(sm + SM_SOM);
        int g = l >> 2, tg = l & 3;
        #pragma unroll
        for (int m = 0; m < 2; ++m)
            #pragma unroll
            for (int nt = 0; nt < 2; ++nt) {
                int o  = oh + nt*8 + 2*tg;
                int pa = px0 + m*16 + g;
                som[pa*33 + o]       = acc1[m][nt][0] + g_bias[o];
                som[pa*33 + o + 1]   = acc1[m][nt][1] + g_bias[o+1];
                som[(pa+8)*33 + o]   = acc1[m][nt][2] + g_bias[o];
                som[(pa+8)*33 + o+1] = acc1[m][nt][3] + g_bias[o+1];
            }
    }
    __syncthreads();   // som visible

    // ================= PHASE 2: gather + deform GEMM (128px x 64o) ============
    #define META_FROM_SOM(TAP, BUF) do { \
        if (tid < 128) { \
            int px = tid; \
            const float* som = (const float*)(sm + SM_SOM); \
            float offy = som[px*33 + 2*(TAP)]; \
            float offx = som[px*33 + 2*(TAP) + 1]; \
            float mr   = som[px*33 + 18 + (TAP)]; \
            float mk   = 1.f / (1.f + expf(-mr)); \
            float py  = offy + (float)((TAP)/3) + (float)(2*ho - 1); \
            float pxx = offx + (float)((TAP)%3) + (float)(px - 1); \
            float y0f = floorf(py), x0f = floorf(pxx); \
            float dy = py - y0f,  dx = pxx - x0f; \
            int y0 = (int)y0f, x0 = (int)x0f; \
            int y1 = y0 + 1,   x1 = x0 + 1; \
            bool vy0 = (y0>=0)&&(y0<H_), vy1 = (y1>=0)&&(y1<H_); \
            bool vx0 = (x0>=0)&&(x0<W_), vx1 = (x1>=0)&&(x1<W_); \
            float* mp = (float*)(sm + SM_META + (BUF)*4096 + px*32); \
            mp[0] = (1.f-dy)*(1.f-dx)*mk * ((vy0&&vx0)?1.f:0.f); \
            mp[1] = (1.f-dy)*dx      *mk * ((vy0&&vx1)?1.f:0.f); \
            mp[2] = dy*(1.f-dx)      *mk * ((vy1&&vx0)?1.f:0.f); \
            mp[3] = dy*dx            *mk * ((vy1&&vx1)?1.f:0.f); \
            int cy0 = min(max(y0,0),H_-1), cy1 = min(max(y1,0),H_-1); \
            int cx0 = min(max(x0,0),W_-1), cx1 = min(max(x1,0),W_-1); \
            ((int*)mp)[4] = (cy0*W_ + cx0) << 8; \
            ((int*)mp)[5] = (cy0*W_ + cx1) << 8; \
            ((int*)mp)[6] = (cy1*W_ + cx0) << 8; \
            ((int*)mp)[7] = (cy1*W_ + cx1) << 8; \
        } \
    } while (0)

    META_FROM_SOM(0, 0);
    __syncthreads();

    float acc[2][4][4];
    #pragma unroll
    for (int m = 0; m < 2; ++m)
        #pragma unroll
        for (int nt = 0; nt < 4; ++nt)
            #pragma unroll
            for (int r = 0; r < 4; ++r) acc[m][nt][r] = 0.f;

    const char* xTb = (const char*)(g_xT + (size_t)b * HW_ * CIN);
    int sub = l >> 3;          // px within 4-px group
    int ch4 = l & 7;           // 16B chunk within 128B half-row
    uint32_t chbyte = (uint32_t)(o0*4 + ch4*16);

    #pragma unroll 1
    for (int k = 0; k < 9; ++k) {
        if (k) __syncthreads();      // GEMM(k-1) done -> A and W reusable

        // stage Wd(k) -> W (single buffer; latency hidden under gather)
        {
            uint32_t dst = smb + SM_W + tid*16;
            const char* src = g_Wsplit + k*16384 + tid*16;
            #pragma unroll
            for (int j = 0; j < 4; ++j) CP16(dst + j*4096u, src + j*4096);
            CP_COMMIT();
        }
        // gather tap k -> A (NHWC: LDG.128 = 4px x 1 corner x 4ch)
        {
            const char* mpb = sm + SM_META + (k & 1)*4096;
            char* ahi = sm + SM_A;
            char* alo = sm + SM_A + 16384;
            #pragma unroll
            for (int g8 = 0; g8 < 8; ++g8) {
                int px = px0 + g8*4 + sub;
                const float* mp = (const float*)(mpb + px*32);
                float4 wv = *(const float4*)mp;
                int4   ov = *(const int4*)(mp + 4);
                float4 c00 = *(const float4*)(xTb + (uint32_t)ov.x + chbyte);
                float4 c01 = *(const float4*)(xTb + (uint32_t)ov.y + chbyte);
                float4 c10 = *(const float4*)(xTb + (uint32_t)ov.z + chbyte);
                float4 c11 = *(const float4*)(xTb + (uint32_t)ov.w + chbyte);
                float v0 = wv.x*c00.x + wv.y*c01.x + wv.z*c10.x + wv.w*c11.x;
                float v1 = wv.x*c00.y + wv.y*c01.y + wv.z*c10.y + wv.w*c11.y;
                float v2 = wv.x*c00.z + wv.y*c01.z + wv.z*c10.z + wv.w*c11.z;
                float v3 = wv.x*c00.w + wv.y*c01.w + wv.z*c10.w + wv.w*c11.w;
                uint32_t h0, l0, h1, l1;
                SPLIT2(v0, v1, h0, l0);
                SPLIT2(v2, v3, h1, l1);
                uint32_t sw = sw128((uint32_t)(px*128) + (uint32_t)(o0*2) + (uint32_t)(ch4*8));
                *(uint2*)(ahi + sw) = make_uint2(h0, h1);
                *(uint2*)(alo + sw) = make_uint2(l0, l1);
            }
        }
        if (k < 8) META_FROM_SOM(k+1, (k+1)&1);
        CP_WAIT(0);
        __syncthreads();             // A + W ready

        // tensor GEMM: per-ks fused 3 passes
        #pragma unroll
        for (int ks = 0; ks < 4; ++ks) {
            uint32_t ah[2][4], al[2][4], bh[2][4], bl[2][4];
            LDMATRIX_X4(ah[0][0],ah[0][1],ah[0][2],ah[0][3], smb + SM_A + aoff[0][ks]);
            LDMATRIX_X4(ah[1][0],ah[1][1],ah[1][2],ah[1][3], smb + SM_A + aoff[1][ks]);
            LDMATRIX_X4(al[0][0],al[0][1],al[0][2],al[0][3], smb + SM_A + 16384u + aoff[0][ks]);
            LDMATRIX_X4(al[1][0],al[1][1],al[1][2],al[1][3], smb + SM_A + 16384u + aoff[1][ks]);
            LDMATRIX_X4(bh[0][0],bh[0][1],bh[0][2],bh[0][3], smb + SM_W + boff[0][ks]);
            LDMATRIX_X4(bh[1][0],bh[1][1],bh[1][2],bh[1][3], smb + SM_W + boff[1][ks]);
            LDMATRIX_X4(bl[0][0],bl[0][1],bl[0][2],bl[0][3], smb + SM_W + 8192u + boff[0][ks]);
            LDMATRIX_X4(bl[1][0],bl[1][1],bl[1][2],bl[1][3], smb + SM_W + 8192u + boff[1][ks]);
            #pragma unroll
            for (int m = 0; m < 2; ++m)
                #pragma unroll
                for (int nt = 0; nt < 4; ++nt) {
                    int np = nt >> 1, bi = (nt & 1)*2;
                    MMA_BF16(acc[m][nt], ah[m][0],ah[m][1],ah[m][2],ah[m][3], bh[np][bi], bh[np][bi+1]);
                    MMA_BF16(acc[m][nt], al[m][0],al[m][1],al[m][2],al[m][3], bh[np][bi], bh[np][bi+1]);
                    MMA_BF16(acc[m][nt], ah[m][0],ah[m][1],ah[m][2],ah[m][3], bl[np][bi], bl[np][bi+1]);
                }
        }
    }

    // ---- epilogue: transpose via smem (reuse A+W region), coalesced store ----
    __syncthreads();
    float* ob = (float*)(sm + SM_A);   // pitch 132 floats, 64*132*4 = 33,792B (A+W = 48KB)
    int g = l >> 2, tg = l & 3;
    #pragma unroll
    for (int m = 0; m < 2; ++m)
        #pragma unroll
        for (int nt = 0; nt < 4; ++nt) {
            int o  = o0 + nt*8 + 2*tg;
            int pa = px0 + m*16 + g;
            ob[o*132 + pa]         = acc[m][nt][0];
            ob[(o+1)*132 + pa]     = acc[m][nt][1];
            ob[o*132 + pa + 8]     = acc[m][nt][2];
            ob[(o+1)*132 + pa + 8] = acc[m][nt][3];
        }
    __syncthreads();
    for (int i = tid; i < 64*32; i += 256) {
        int o = i >> 5, seg = i & 31;
        float4 v = *(float4*)&ob[o*132 + seg*4];
        *(float4*)&out[(((size_t)b*CO + o)*HO + ho)*WO + seg*4] = v;
    }
}

// ---------------------------------------------------------------------------
extern "C" void kernel_launch(void* const* d_in, const int* in_sizes, int n_in,
                              void* d_out, int out_size) {
    const float* x      = (const float*)d_in[0];
    const float* w_off  = (const float*)d_in[1];
    const float* b_off  = (const float*)d_in[2];
    const float* w_mask = (const float*)d_in[3];
    const float* b_mask = (const float*)d_in[4];
    const float* w_conv = (const float*)d_in[5];
    float* out = (float*)d_out;

    prep_kernel<<<144, 256>>>(w_off, b_off, w_mask, b_mask, w_conv);
    transpose_kernel<<<dim3(4, 128, 8), 256>>>(x);

    cudaFuncSetAttribute((const void*)deform_kernel,
                         cudaFuncAttributeMaxDynamicSharedMemorySize, SM_TOTAL);
    deform_kernel<<<dim3(HO, B_), 256, SM_TOTAL>>>(x, out);
}

// round 12
// speedup vs baseline: 1.3996x; 1.3996x over previous
#include <cuda_runtime.h>
#include <cuda_fp16.h>
#include <math.h>
#include <stdint.h>

#define B_  8
#define CIN 64
#define H_  128
#define W_  128
#define HO  64
#define WO  128
#define CO  64
#define HW_ (H_*W_)

// Scratch (no allocations allowed -> __device__ globals)
__device__ float g_bias[32];
__device__ __align__(16) char g_Wsplit[9*16384];   // deform W: per tap fp16 hi 8KB + lo 8KB, SW128
__device__ __align__(16) char g_WomSplit[9*8192];  // conv W: per tap fp16 hi 4KB + lo 4KB, SW128
__device__ __align__(16) float g_xT[(size_t)B_*H_*W_*CIN];  // NHWC transpose of x (32MB)

__device__ __forceinline__ uint32_t smem_u32(const void* p) {
    uint32_t a;
    asm("{ .reg .u64 t; cvta.to.shared.u64 t, %1; cvt.u32.u64 %0, t; }" : "=r"(a) : "l"(p));
    return a;
}
__device__ __forceinline__ uint32_t sw128(uint32_t off) { return off ^ ((off >> 3) & 0x70); }

#define LDMATRIX_X4(r0,r1,r2,r3,addr) \
    asm volatile("ldmatrix.sync.aligned.m8n8.x4.shared.b16 {%0,%1,%2,%3}, [%4];" \
                 : "=r"(r0),"=r"(r1),"=r"(r2),"=r"(r3) : "r"(addr))

#define MMA_FP16(c, a0,a1,a2,a3, b0,b1) \
    asm volatile("mma.sync.aligned.m16n8k16.row.col.f32.f16.f16.f32 " \
                 "{%0,%1,%2,%3},{%4,%5,%6,%7},{%8,%9},{%0,%1,%2,%3};" \
                 : "+f"((c)[0]),"+f"((c)[1]),"+f"((c)[2]),"+f"((c)[3]) \
                 : "r"(a0),"r"(a1),"r"(a2),"r"(a3), "r"(b0),"r"(b1))

#define CP16(dst, src) \
    asm volatile("cp.async.cg.shared.global [%0], [%1], 16;" :: "r"(dst), "l"(src) : "memory")
#define CP_COMMIT() asm volatile("cp.async.commit_group;" ::: "memory")
#define CP_WAIT(n)  asm volatile("cp.async.wait_group %0;" :: "n"(n) : "memory")

// pack (v0, v1) -> fp16x2 word (v1 high, v0 low)
#define PACKH2(v0, v1, h) \
    asm("cvt.rn.f16x2.f32 %0, %1, %2;" : "=r"(h) : "f"(v1), "f"(v0))

// ---------------------------------------------------------------------------
// Kernel 0: weight repack (fp16 hi/lo split, SW128 swizzled)
// ---------------------------------------------------------------------------
__global__ void prep_kernel(const float* __restrict__ w_off, const float* __restrict__ b_off,
                            const float* __restrict__ w_mask, const float* __restrict__ b_mask,
                            const float* __restrict__ w_conv) {
    int idx = blockIdx.x * blockDim.x + threadIdx.x;
    if (idx < 9*64*64) {
        int k = idx / 4096; int r = idx & 4095; int o = r >> 6; int c = r & 63;
        float w = w_conv[(o*64 + c)*9 + k];
        __half hi = __float2half(w);
        __half lo = __float2half(w - __half2float(hi));
        uint32_t sw = sw128((uint32_t)(o*128 + c*2));
        *(__half*)(g_Wsplit + k*16384 + sw)        = hi;
        *(__half*)(g_Wsplit + k*16384 + 8192 + sw) = lo;
    }
    if (idx < 9*32*64) {
        int k = idx / 2048; int r = idx & 2047; int o = r >> 6; int c = r & 63;
        float w = 0.f;
        if (o < 18)       w = w_off[(o*64 + c)*9 + k];
        else if (o < 27)  w = w_mask[((o-18)*64 + c)*9 + k];
        __half hi = __float2half(w);
        __half lo = __float2half(w - __half2float(hi));
        uint32_t sw = sw128((uint32_t)(o*128 + c*2));
        *(__half*)(g_WomSplit + k*8192 + sw)        = hi;
        *(__half*)(g_WomSplit + k*8192 + 4096 + sw) = lo;
    }
    if (idx < 32) {
        float v = 0.f;
        if (idx < 18)      v = b_off[idx];
        else if (idx < 27) v = b_mask[idx - 18];
        g_bias[idx] = v;
    }
}

// ---------------------------------------------------------------------------
// Kernel 0b: NCHW -> NHWC transpose of x
// ---------------------------------------------------------------------------
__global__ void __launch_bounds__(256) transpose_kernel(const float* __restrict__ x) {
    __shared__ float t[64][33];
    int x0 = blockIdx.x * 32, y = blockIdx.y, b = blockIdx.z;
    int tx = threadIdx.x & 31, tc = threadIdx.x >> 5;
    const float* xb = x + (size_t)b * CIN * HW_ + y*W_ + x0;
    #pragma unroll
    for (int cc = 0; cc < 8; ++cc)
        t[tc + cc*8][tx] = __ldg(xb + (size_t)(tc + cc*8)*HW_ + tx);
    __syncthreads();
    float* dst = g_xT + ((size_t)b*HW_ + y*W_ + x0) * CIN;
    int c = threadIdx.x & 63, xx = threadIdx.x >> 6;
    #pragma unroll
    for (int q = 0; q < 8; ++q)
        dst[(size_t)(xx + q*4)*CIN + c] = t[c][xx + q*4];
}

// ---------------------------------------------------------------------------
// Fused kernel (R8 structure, fp16 2-pass): 128px x 64o per CTA, 2 CTAs/SM.
// ---------------------------------------------------------------------------
#define SM_A     0          // A fp16: 16KB, row px (128B, sw128)
#define SM_W     16384      // W double buffer: 2 x (hi 8KB + lo 8KB)
#define SM_WOM   49152      // conv W double buffer: 2 x (hi 4KB + lo 4KB)
#define SM_META  65536      // meta double buffer: 2 x 128px x 32B
#define SM_SOM   73728      // som[128 px][33 floats] = 16,896B
#define SM_TOTAL 90624      // -> 2 CTAs/SM

__global__ void __launch_bounds__(256, 2) deform_kernel(const float* __restrict__ x,
                                                        float* __restrict__ out) {
    extern __shared__ char sm[];
    const uint32_t smb = smem_u32(sm);
    int tid = threadIdx.x;
    int l = tid & 31, w = tid >> 5;
    int ho = blockIdx.x, b = blockIdx.y;
    const float* xb = x + (size_t)b * CIN * HW_;

    int px0 = (w & 3) * 32;          // px tile base (gather + mma rows)
    int o0  = (w >> 2) * 32;         // phase-2 o tile base / gather channel half
    int oh  = (w >> 2) * 16;         // phase-1 o tile base
    int gpx = px0 + l;

    // ---- ldmatrix lane offsets (per-ks, sw128 wraps full offset) ----
    uint32_t aoff[2][4], boff[2][4], b1off[4];
    {
        int arow = px0 + (l & 15);
        int acol = (l & 16) ? 16 : 0;
        #pragma unroll
        for (int m = 0; m < 2; ++m)
            #pragma unroll
            for (int ks = 0; ks < 4; ++ks)
                aoff[m][ks] = sw128((uint32_t)((arow + m*16)*128 + ks*32 + acol));
        int brow = o0 + (l & 7) + ((l & 16) ? 8 : 0);
        int bcol = (l & 8) ? 16 : 0;
        #pragma unroll
        for (int np = 0; np < 2; ++np)
            #pragma unroll
            for (int ks = 0; ks < 4; ++ks)
                boff[np][ks] = sw128((uint32_t)((brow + np*16)*128 + ks*32 + bcol));
        int b1row = oh + (l & 7) + ((l & 16) ? 8 : 0);
        #pragma unroll
        for (int ks = 0; ks < 4; ++ks)
            b1off[ks] = sw128((uint32_t)(b1row*128 + ks*32 + bcol));
    }

    // ================= PHASE 1: offset/mask conv (128px x 32o) ================
    {
        uint32_t dst = smb + SM_WOM + tid*16;
        const char* src = g_WomSplit + tid*16;
        CP16(dst, src); CP16(dst + 4096u, src + 4096);
        CP_COMMIT();
    }

    float acc1[2][2][4];
    #pragma unroll
    for (int m = 0; m < 2; ++m)
        #pragma unroll
        for (int nt = 0; nt < 2; ++nt)
            #pragma unroll
            for (int r = 0; r < 4; ++r) acc1[m][nt][r] = 0.f;

    #pragma unroll 1
    for (int k = 0; k < 9; ++k) {
        if (k) __syncthreads();

        // build A_k[px][c]: im2col row loads (NCHW coalesced), fp16, sw128
        {
            int gy = 2*ho - 1 + (k/3);
            int gx = gpx - 1 + (k%3);
            bool vld = (gy >= 0) && (gx >= 0) && (gx < W_);
            char* ah = sm + SM_A;
            uint32_t rowoff = (uint32_t)(gpx*128 + o0*2);
            const float* xc = xb + (size_t)o0 * HW_ + gy*W_ + gx;
            #pragma unroll
            for (int j4 = 0; j4 < 4; ++j4) {
                uint32_t hv[4];
                #pragma unroll
                for (int jj = 0; jj < 4; ++jj) {
                    float v0 = vld ? __ldg(xc)       : 0.f;
                    float v1 = vld ? __ldg(xc + HW_) : 0.f;
                    xc += 2*HW_;
                    PACKH2(v0, v1, hv[jj]);
                }
                uint32_t sw = sw128(rowoff + j4*16);
                *(uint4*)(ah + sw) = make_uint4(hv[0],hv[1],hv[2],hv[3]);
            }
        }
        if (k < 8) {
            uint32_t dst = smb + SM_WOM + ((k+1)&1)*8192u + tid*16;
            const char* src = g_WomSplit + (k+1)*8192 + tid*16;
            CP16(dst, src); CP16(dst + 4096u, src + 4096);
            CP_COMMIT();
            CP_WAIT(1);
        } else {
            CP_WAIT(0);
        }
        __syncthreads();

        uint32_t wbase = smb + SM_WOM + (k & 1)*8192u;
        #pragma unroll
        for (int ks = 0; ks < 4; ++ks) {
            uint32_t ah[2][4], bh[4], bl[4];
            LDMATRIX_X4(ah[0][0],ah[0][1],ah[0][2],ah[0][3], smb + SM_A + aoff[0][ks]);
            LDMATRIX_X4(ah[1][0],ah[1][1],ah[1][2],ah[1][3], smb + SM_A + aoff[1][ks]);
            LDMATRIX_X4(bh[0],bh[1],bh[2],bh[3], wbase + b1off[ks]);
            LDMATRIX_X4(bl[0],bl[1],bl[2],bl[3], wbase + 4096u + b1off[ks]);
            #pragma unroll
            for (int m = 0; m < 2; ++m)
                #pragma unroll
                for (int nt = 0; nt < 2; ++nt) {
                    MMA_FP16(acc1[m][nt], ah[m][0],ah[m][1],ah[m][2],ah[m][3], bh[nt*2], bh[nt*2+1]);
                    MMA_FP16(acc1[m][nt], ah[m][0],ah[m][1],ah[m][2],ah[m][3], bl[nt*2], bl[nt*2+1]);
                }
        }
    }

    // write som[px][o] = acc + bias (pitch 33)
    {
        float* som = (float*)(sm + SM_SOM);
        int g = l >> 2, tg = l & 3;
        #pragma unroll
        for (int m = 0; m < 2; ++m)
            #pragma unroll
            for (int nt = 0; nt < 2; ++nt) {
                int o  = oh + nt*8 + 2*tg;
                int pa = px0 + m*16 + g;
                som[pa*33 + o]       = acc1[m][nt][0] + g_bias[o];
                som[pa*33 + o + 1]   = acc1[m][nt][1] + g_bias[o+1];
                som[(pa+8)*33 + o]   = acc1[m][nt][2] + g_bias[o];
                som[(pa+8)*33 + o+1] = acc1[m][nt][3] + g_bias[o+1];
            }
    }
    // stage deform W tap 0
    {
        uint32_t dst = smb + SM_W + tid*16;
        const char* src = g_Wsplit + tid*16;
        #pragma unroll
        for (int j = 0; j < 4; ++j) CP16(dst + j*4096u, src + j*4096);
        CP_COMMIT();
    }
    __syncthreads();   // som visible

    // ================= PHASE 2: gather + deform GEMM =================
    #define META_FROM_SOM(TAP, BUF) do { \
        if (tid < 128) { \
            int px = tid; \
            const float* som = (const float*)(sm + SM_SOM); \
            float offy = som[px*33 + 2*(TAP)]; \
            float offx = som[px*33 + 2*(TAP) + 1]; \
            float mr   = som[px*33 + 18 + (TAP)]; \
            float mk   = 1.f / (1.f + expf(-mr)); \
            float py  = offy + (float)((TAP)/3) + (float)(2*ho - 1); \
            float pxx = offx + (float)((TAP)%3) + (float)(px - 1); \
            float y0f = floorf(py), x0f = floorf(pxx); \
            float dy = py - y0f,  dx = pxx - x0f; \
            int y0 = (int)y0f, x0 = (int)x0f; \
            int y1 = y0 + 1,   x1 = x0 + 1; \
            bool vy0 = (y0>=0)&&(y0<H_), vy1 = (y1>=0)&&(y1<H_); \
            bool vx0 = (x0>=0)&&(x0<W_), vx1 = (x1>=0)&&(x1<W_); \
            float* mp = (float*)(sm + SM_META + (BUF)*4096 + px*32); \
            mp[0] = (1.f-dy)*(1.f-dx)*mk * ((vy0&&vx0)?1.f:0.f); \
            mp[1] = (1.f-dy)*dx      *mk * ((vy0&&vx1)?1.f:0.f); \
            mp[2] = dy*(1.f-dx)      *mk * ((vy1&&vx0)?1.f:0.f); \
            mp[3] = dy*dx            *mk * ((vy1&&vx1)?1.f:0.f); \
            int cy0 = min(max(y0,0),H_-1), cy1 = min(max(y1,0),H_-1); \
            int cx0 = min(max(x0,0),W_-1), cx1 = min(max(x1,0),W_-1); \
            ((int*)mp)[4] = (cy0*W_ + cx0) << 8; \
            ((int*)mp)[5] = (cy0*W_ + cx1) << 8; \
            ((int*)mp)[6] = (cy1*W_ + cx0) << 8; \
            ((int*)mp)[7] = (cy1*W_ + cx1) << 8; \
        } \
    } while (0)

    META_FROM_SOM(0, 0);
    __syncthreads();

    float acc[2][4][4];
    #pragma unroll
    for (int m = 0; m < 2; ++m)
        #pragma unroll
        for (int nt = 0; nt < 4; ++nt)
            #pragma unroll
            for (int r = 0; r < 4; ++r) acc[m][nt][r] = 0.f;

    const char* xTb = (const char*)(g_xT + (size_t)b * HW_ * CIN);
    int sub = l >> 3;          // px within 4-px group
    int ch4 = l & 7;           // 16B chunk within 128B half-row
    uint32_t chbyte = (uint32_t)(o0*4 + ch4*16);

    #pragma unroll 1
    for (int k = 0; k < 9; ++k) {
        if (k) __syncthreads();

        // gather tap k -> A (NHWC: LDG.128 = 4px x 1 corner x 4ch), fp16 pack
        {
            const char* mpb = sm + SM_META + (k & 1)*4096;
            char* ah = sm + SM_A;
            #pragma unroll
            for (int g8 = 0; g8 < 8; ++g8) {
                int px = px0 + g8*4 + sub;
                const float* mp = (const float*)(mpb + px*32);
                float4 wv = *(const float4*)mp;
                int4   ov = *(const int4*)(mp + 4);
                float4 c00 = *(const float4*)(xTb + (uint32_t)ov.x + chbyte);
                float4 c01 = *(const float4*)(xTb + (uint32_t)ov.y + chbyte);
                float4 c10 = *(const float4*)(xTb + (uint32_t)ov.z + chbyte);
                float4 c11 = *(const float4*)(xTb + (uint32_t)ov.w + chbyte);
                float v0 = wv.x*c00.x + wv.y*c01.x + wv.z*c10.x + wv.w*c11.x;
                float v1 = wv.x*c00.y + wv.y*c01.y + wv.z*c10.y + wv.w*c11.y;
                float v2 = wv.x*c00.z + wv.y*c01.z + wv.z*c10.z + wv.w*c11.z;
                float v3 = wv.x*c00.w + wv.y*c01.w + wv.z*c10.w + wv.w*c11.w;
                uint32_t h0, h1;
                PACKH2(v0, v1, h0);
                PACKH2(v2, v3, h1);
                uint32_t sw = sw128((uint32_t)(px*128) + (uint32_t)(o0*2) + (uint32_t)(ch4*8));
                *(uint2*)(ah + sw) = make_uint2(h0, h1);
            }
        }
        if (k < 8) META_FROM_SOM(k+1, (k+1)&1);

        if (k < 8) {
            uint32_t dst = smb + SM_W + ((k+1)&1)*16384u + tid*16;
            const char* src = g_Wsplit + (k+1)*16384 + tid*16;
            #pragma unroll
            for (int j = 0; j < 4; ++j) CP16(dst + j*4096u, src + j*4096);
            CP_COMMIT();
            CP_WAIT(1);
        } else {
            CP_WAIT(0);
        }
        __syncthreads();

        // tensor GEMM: per-ks fused 2 passes (A once, B hi + B lo)
        uint32_t wbase = smb + SM_W + (k & 1)*16384u;
        #pragma unroll
        for (int ks = 0; ks < 4; ++ks) {
            uint32_t ah[2][4], bh[2][4], bl[2][4];
            LDMATRIX_X4(ah[0][0],ah[0][1],ah[0][2],ah[0][3], smb + SM_A + aoff[0][ks]);
            LDMATRIX_X4(ah[1][0],ah[1][1],ah[1][2],ah[1][3], smb + SM_A + aoff[1][ks]);
            LDMATRIX_X4(bh[0][0],bh[0][1],bh[0][2],bh[0][3], wbase + boff[0][ks]);
            LDMATRIX_X4(bh[1][0],bh[1][1],bh[1][2],bh[1][3], wbase + boff[1][ks]);
            LDMATRIX_X4(bl[0][0],bl[0][1],bl[0][2],bl[0][3], wbase + 8192u + boff[0][ks]);
            LDMATRIX_X4(bl[1][0],bl[1][1],bl[1][2],bl[1][3], wbase + 8192u + boff[1][ks]);
            #pragma unroll
            for (int m = 0; m < 2; ++m)
                #pragma unroll
                for (int nt = 0; nt < 4; ++nt) {
                    int np = nt >> 1, bi = (nt & 1)*2;
                    MMA_FP16(acc[m][nt], ah[m][0],ah[m][1],ah[m][2],ah[m][3], bh[np][bi], bh[np][bi+1]);
                    MMA_FP16(acc[m][nt], ah[m][0],ah[m][1],ah[m][2],ah[m][3], bl[np][bi], bl[np][bi+1]);
                }
        }
    }

    // ---- epilogue: transpose via smem (reuse A+W region), coalesced store ----
    __syncthreads();
    float* ob = (float*)(sm + SM_A);   // pitch 132 floats, 33,792B fits in A+W (48KB)
    int g = l >> 2, tg = l & 3;
    #pragma unroll
    for (int m = 0; m < 2; ++m)
        #pragma unroll
        for (int nt = 0; nt < 4; ++nt) {
            int o  = o0 + nt*8 + 2*tg;
            int pa = px0 + m*16 + g;
            ob[o*132 + pa]         = acc[m][nt][0];
            ob[(o+1)*132 + pa]     = acc[m][nt][1];
            ob[o*132 + pa + 8]     = acc[m][nt][2];
            ob[(o+1)*132 + pa + 8] = acc[m][nt][3];
        }
    __syncthreads();
    for (int i = tid; i < 64*32; i += 256) {
        int o = i >> 5, seg = i & 31;
        float4 v = *(float4*)&ob[o*132 + seg*4];
        *(float4*)&out[(((size_t)b*CO + o)*HO + ho)*WO + seg*4] = v;
    }
}

// ---------------------------------------------------------------------------
extern "C" void kernel_launch(void* const* d_in, const int* in_sizes, int n_in,
                              void* d_out, int out_size) {
    const float* x      = (const float*)d_in[0];
    const float* w_off  = (const float*)d_in[1];
    const float* b_off  = (const float*)d_in[2];
    const float* w_mask = (const float*)d_in[3];
    const float* b_mask = (const float*)d_in[4];
    const float* w_conv = (const float*)d_in[5];
    float* out = (float*)d_out;

    prep_kernel<<<144, 256>>>(w_off, b_off, w_mask, b_mask, w_conv);
    transpose_kernel<<<dim3(4, 128, 8), 256>>>(x);

    cudaFuncSetAttribute((const void*)deform_kernel,
                         cudaFuncAttributeMaxDynamicSharedMemorySize, SM_TOTAL);
    deform_kernel<<<dim3(HO, B_), 256, SM_TOTAL>>>(x, out);
}

// round 13
// speedup vs baseline: 1.8306x; 1.3079x over previous
#include <cuda_runtime.h>
#include <cuda_fp16.h>
#include <math.h>
#include <stdint.h>

#define B_  8
#define CIN 64
#define H_  128
#define W_  128
#define HO  64
#define WO  128
#define CO  64
#define HW_ (H_*W_)

// Scratch (no allocations allowed -> __device__ globals)
__device__ float g_bias[32];
__device__ __align__(16) char g_Wsplit[9*16384];   // deform W: per tap fp16 hi 8KB + lo 8KB, SW128
__device__ __align__(16) char g_WomSplit[9*8192];  // conv W: per tap fp16 hi 4KB + lo 4KB, SW128
__device__ __align__(16) __half g_xT[(size_t)B_*H_*W_*CIN];  // NHWC fp16 x (16MB)

__device__ __forceinline__ uint32_t smem_u32(const void* p) {
    uint32_t a;
    asm("{ .reg .u64 t; cvta.to.shared.u64 t, %1; cvt.u32.u64 %0, t; }" : "=r"(a) : "l"(p));
    return a;
}
__device__ __forceinline__ uint32_t sw128(uint32_t off) { return off ^ ((off >> 3) & 0x70); }

#define LDMATRIX_X4(r0,r1,r2,r3,addr) \
    asm volatile("ldmatrix.sync.aligned.m8n8.x4.shared.b16 {%0,%1,%2,%3}, [%4];" \
                 : "=r"(r0),"=r"(r1),"=r"(r2),"=r"(r3) : "r"(addr))

#define MMA_FP16(c, a0,a1,a2,a3, b0,b1) \
    asm volatile("mma.sync.aligned.m16n8k16.row.col.f32.f16.f16.f32 " \
                 "{%0,%1,%2,%3},{%4,%5,%6,%7},{%8,%9},{%0,%1,%2,%3};" \
                 : "+f"((c)[0]),"+f"((c)[1]),"+f"((c)[2]),"+f"((c)[3]) \
                 : "r"(a0),"r"(a1),"r"(a2),"r"(a3), "r"(b0),"r"(b1))

#define CP16(dst, src) \
    asm volatile("cp.async.cg.shared.global [%0], [%1], 16;" :: "r"(dst), "l"(src) : "memory")
#define CP16Z(dst, src, sz) \
    asm volatile("cp.async.cg.shared.global [%0], [%1], 16, %2;" :: "r"(dst), "l"(src), "r"(sz) : "memory")
#define CP_COMMIT() asm volatile("cp.async.commit_group;" ::: "memory")
#define CP_WAIT(n)  asm volatile("cp.async.wait_group %0;" :: "n"(n) : "memory")

// pack (v0, v1) -> fp16x2 word (v1 high, v0 low)
#define PACKH2(v0, v1, h) \
    asm("cvt.rn.f16x2.f32 %0, %1, %2;" : "=r"(h) : "f"(v1), "f"(v0))

// ---------------------------------------------------------------------------
// Kernel 0: weight repack (fp16 hi/lo split, SW128 swizzled)
// ---------------------------------------------------------------------------
__global__ void prep_kernel(const float* __restrict__ w_off, const float* __restrict__ b_off,
                            const float* __restrict__ w_mask, const float* __restrict__ b_mask,
                            const float* __restrict__ w_conv) {
    int idx = blockIdx.x * blockDim.x + threadIdx.x;
    if (idx < 9*64*64) {
        int k = idx / 4096; int r = idx & 4095; int o = r >> 6; int c = r & 63;
        float w = w_conv[(o*64 + c)*9 + k];
        __half hi = __float2half(w);
        __half lo = __float2half(w - __half2float(hi));
        uint32_t sw = sw128((uint32_t)(o*128 + c*2));
        *(__half*)(g_Wsplit + k*16384 + sw)        = hi;
        *(__half*)(g_Wsplit + k*16384 + 8192 + sw) = lo;
    }
    if (idx < 9*32*64) {
        int k = idx / 2048; int r = idx & 2047; int o = r >> 6; int c = r & 63;
        float w = 0.f;
        if (o < 18)       w = w_off[(o*64 + c)*9 + k];
        else if (o < 27)  w = w_mask[((o-18)*64 + c)*9 + k];
        __half hi = __float2half(w);
        __half lo = __float2half(w - __half2float(hi));
        uint32_t sw = sw128((uint32_t)(o*128 + c*2));
        *(__half*)(g_WomSplit + k*8192 + sw)        = hi;
        *(__half*)(g_WomSplit + k*8192 + 4096 + sw) = lo;
    }
    if (idx < 32) {
        float v = 0.f;
        if (idx < 18)      v = b_off[idx];
        else if (idx < 27) v = b_mask[idx - 18];
        g_bias[idx] = v;
    }
}

// ---------------------------------------------------------------------------
// Kernel 0b: NCHW fp32 -> NHWC fp16 transpose of x
// ---------------------------------------------------------------------------
__global__ void __launch_bounds__(256) transpose_kernel(const float* __restrict__ x) {
    __shared__ float t[64][33];
    int x0 = blockIdx.x * 32, y = blockIdx.y, b = blockIdx.z;
    int tx = threadIdx.x & 31, tc = threadIdx.x >> 5;
    const float* xb = x + (size_t)b * CIN * HW_ + y*W_ + x0;
    #pragma unroll
    for (int cc = 0; cc < 8; ++cc)
        t[tc + cc*8][tx] = __ldg(xb + (size_t)(tc + cc*8)*HW_ + tx);
    __syncthreads();
    __half* dst = g_xT + ((size_t)b*HW_ + y*W_ + x0) * CIN;
    int c2 = (threadIdx.x & 31) * 2;     // channel pair
    int xx = threadIdx.x >> 5;           // 0..7
    #pragma unroll
    for (int q = 0; q < 4; ++q) {
        int xp = xx + q*8;
        __half2 hv = __floats2half2_rn(t[c2][xp], t[c2+1][xp]);
        *(__half2*)(dst + (size_t)xp*CIN + c2) = hv;
    }
}

// ---------------------------------------------------------------------------
// Fused kernel (fp16 xT gather): 128px x 64o per CTA, 2 CTAs/SM.
// ---------------------------------------------------------------------------
#define SM_A     0          // A fp16: 16KB, row px (128B, sw128)
#define SM_W     16384      // W double buffer: 2 x (hi 8KB + lo 8KB)
#define SM_WOM   49152      // conv W double buffer: 2 x (hi 4KB + lo 4KB)
#define SM_META  65536      // meta double buffer: 2 x 128px x 32B
#define SM_SOM   73728      // som[128 px][33 floats] = 16,896B
#define SM_TOTAL 90624      // -> 2 CTAs/SM

__global__ void __launch_bounds__(256, 2) deform_kernel(float* __restrict__ out) {
    extern __shared__ char sm[];
    const uint32_t smb = smem_u32(sm);
    int tid = threadIdx.x;
    int l = tid & 31, w = tid >> 5;
    int ho = blockIdx.x, b = blockIdx.y;

    int px0 = (w & 3) * 32;          // mma px tile base
    int o0  = (w >> 2) * 32;         // phase-2 mma o tile base
    int oh  = (w >> 2) * 16;         // phase-1 o tile base
    int w16 = w * 16;                // gather px base (16 px per warp)
    int sub = l >> 3;                // px within 4-group
    int ch4 = l & 7;                 // 16B chunk within 128B row

    const char* xTb = (const char*)(g_xT + (size_t)b * HW_ * CIN);

    // ---- ldmatrix lane offsets (per-ks, sw128 wraps full offset) ----
    uint32_t aoff[2][4], boff[2][4], b1off[4];
    {
        int arow = px0 + (l & 15);
        int acol = (l & 16) ? 16 : 0;
        #pragma unroll
        for (int m = 0; m < 2; ++m)
            #pragma unroll
            for (int ks = 0; ks < 4; ++ks)
                aoff[m][ks] = sw128((uint32_t)((arow + m*16)*128 + ks*32 + acol));
        int brow = o0 + (l & 7) + ((l & 16) ? 8 : 0);
        int bcol = (l & 8) ? 16 : 0;
        #pragma unroll
        for (int np = 0; np < 2; ++np)
            #pragma unroll
            for (int ks = 0; ks < 4; ++ks)
                boff[np][ks] = sw128((uint32_t)((brow + np*16)*128 + ks*32 + bcol));
        int b1row = oh + (l & 7) + ((l & 16) ? 8 : 0);
        #pragma unroll
        for (int ks = 0; ks < 4; ++ks)
            b1off[ks] = sw128((uint32_t)(b1row*128 + ks*32 + bcol));
    }

    // ================= PHASE 1: offset/mask conv (128px x 32o) ================
    {
        uint32_t dst = smb + SM_WOM + tid*16;
        const char* src = g_WomSplit + tid*16;
        CP16(dst, src); CP16(dst + 4096u, src + 4096);
        CP_COMMIT();
    }

    float acc1[2][2][4];
    #pragma unroll
    for (int m = 0; m < 2; ++m)
        #pragma unroll
        for (int nt = 0; nt < 2; ++nt)
            #pragma unroll
            for (int r = 0; r < 4; ++r) acc1[m][nt][r] = 0.f;

    #pragma unroll 1
    for (int k = 0; k < 9; ++k) {
        if (k) __syncthreads();

        // A_k[px][c] = xT rows (im2col): pure cp.async copy, zero-fill at borders
        {
            int gy = 2*ho - 1 + (k/3);
            int gyc = max(gy, 0);
            #pragma unroll
            for (int it = 0; it < 4; ++it) {
                int px = w16 + it*4 + sub;
                int gx = px - 1 + (k%3);
                bool vld = (gy >= 0) && (gx >= 0) && (gx < W_);
                int gxc = min(max(gx, 0), W_-1);
                const char* src = xTb + ((size_t)(gyc*W_ + gxc)*128 + ch4*16);
                uint32_t dst = smb + SM_A + sw128((uint32_t)(px*128 + ch4*16));
                unsigned sz = vld ? 16u : 0u;
                CP16Z(dst, src, sz);
            }
            CP_COMMIT();
        }
        if (k < 8) {
            uint32_t dst = smb + SM_WOM + ((k+1)&1)*8192u + tid*16;
            const char* src = g_WomSplit + (k+1)*8192 + tid*16;
            CP16(dst, src); CP16(dst + 4096u, src + 4096);
            CP_COMMIT();
            CP_WAIT(1);    // A(k) + Wom(k) done; Wom(k+1) in flight
        } else {
            CP_WAIT(0);
        }
        __syncthreads();

        uint32_t wbase = smb + SM_WOM + (k & 1)*8192u;
        #pragma unroll
        for (int ks = 0; ks < 4; ++ks) {
            uint32_t ah[2][4], bh[4], bl[4];
            LDMATRIX_X4(ah[0][0],ah[0][1],ah[0][2],ah[0][3], smb + SM_A + aoff[0][ks]);
            LDMATRIX_X4(ah[1][0],ah[1][1],ah[1][2],ah[1][3], smb + SM_A + aoff[1][ks]);
            LDMATRIX_X4(bh[0],bh[1],bh[2],bh[3], wbase + b1off[ks]);
            LDMATRIX_X4(bl[0],bl[1],bl[2],bl[3], wbase + 4096u + b1off[ks]);
            #pragma unroll
            for (int m = 0; m < 2; ++m)
                #pragma unroll
                for (int nt = 0; nt < 2; ++nt) {
                    MMA_FP16(acc1[m][nt], ah[m][0],ah[m][1],ah[m][2],ah[m][3], bh[nt*2], bh[nt*2+1]);
                    MMA_FP16(acc1[m][nt], ah[m][0],ah[m][1],ah[m][2],ah[m][3], bl[nt*2], bl[nt*2+1]);
                }
        }
    }

    // write som[px][o] = acc + bias (pitch 33)
    {
        float* som = (float*)(sm + SM_SOM);
        int g = l >> 2, tg = l & 3;
        #pragma unroll
        for (int m = 0; m < 2; ++m)
            #pragma unroll
            for (int nt = 0; nt < 2; ++nt) {
                int o  = oh + nt*8 + 2*tg;
                int pa = px0 + m*16 + g;
                som[pa*33 + o]       = acc1[m][nt][0] + g_bias[o];
                som[pa*33 + o + 1]   = acc1[m][nt][1] + g_bias[o+1];
                som[(pa+8)*33 + o]   = acc1[m][nt][2] + g_bias[o];
                som[(pa+8)*33 + o+1] = acc1[m][nt][3] + g_bias[o+1];
            }
    }
    // stage deform W tap 0
    {
        uint32_t dst = smb + SM_W + tid*16;
        const char* src = g_Wsplit + tid*16;
        #pragma unroll
        for (int j = 0; j < 4; ++j) CP16(dst + j*4096u, src + j*4096);
        CP_COMMIT();
    }
    __syncthreads();   // som visible

    // ================= PHASE 2: gather + deform GEMM =================
    // meta: 4 corner weights + 4 corner byte-offsets into fp16 NHWC (x128B)
    #define META_FROM_SOM(TAP, BUF) do { \
        if (tid < 128) { \
            int px = tid; \
            const float* som = (const float*)(sm + SM_SOM); \
            float offy = som[px*33 + 2*(TAP)]; \
            float offx = som[px*33 + 2*(TAP) + 1]; \
            float mr   = som[px*33 + 18 + (TAP)]; \
            float mk   = 1.f / (1.f + expf(-mr)); \
            float py  = offy + (float)((TAP)/3) + (float)(2*ho - 1); \
            float pxx = offx + (float)((TAP)%3) + (float)(px - 1); \
            float y0f = floorf(py), x0f = floorf(pxx); \
            float dy = py - y0f,  dx = pxx - x0f; \
            int y0 = (int)y0f, x0 = (int)x0f; \
            int y1 = y0 + 1,   x1 = x0 + 1; \
            bool vy0 = (y0>=0)&&(y0<H_), vy1 = (y1>=0)&&(y1<H_); \
            bool vx0 = (x0>=0)&&(x0<W_), vx1 = (x1>=0)&&(x1<W_); \
            float* mp = (float*)(sm + SM_META + (BUF)*4096 + px*32); \
            mp[0] = (1.f-dy)*(1.f-dx)*mk * ((vy0&&vx0)?1.f:0.f); \
            mp[1] = (1.f-dy)*dx      *mk * ((vy0&&vx1)?1.f:0.f); \
            mp[2] = dy*(1.f-dx)      *mk * ((vy1&&vx0)?1.f:0.f); \
            mp[3] = dy*dx            *mk * ((vy1&&vx1)?1.f:0.f); \
            int cy0 = min(max(y0,0),H_-1), cy1 = min(max(y1,0),H_-1); \
            int cx0 = min(max(x0,0),W_-1), cx1 = min(max(x1,0),W_-1); \
            ((int*)mp)[4] = (cy0*W_ + cx0) << 7; \
            ((int*)mp)[5] = (cy0*W_ + cx1) << 7; \
            ((int*)mp)[6] = (cy1*W_ + cx0) << 7; \
            ((int*)mp)[7] = (cy1*W_ + cx1) << 7; \
        } \
    } while (0)

    META_FROM_SOM(0, 0);
    __syncthreads();

    float acc[2][4][4];
    #pragma unroll
    for (int m = 0; m < 2; ++m)
        #pragma unroll
        for (int nt = 0; nt < 4; ++nt)
            #pragma unroll
            for (int r = 0; r < 4; ++r) acc[m][nt][r] = 0.f;

    #pragma unroll 1
    for (int k = 0; k < 9; ++k) {
        if (k) __syncthreads();

        // gather tap k -> A. fp16 NHWC: LDG.128 = 4px x 1 corner x 8ch (full lines)
        {
            const char* mpb = sm + SM_META + (k & 1)*4096;
            uint32_t cb = (uint32_t)(ch4*16);
            #pragma unroll
            for (int it = 0; it < 4; ++it) {
                int px = w16 + it*4 + sub;
                const float* mp = (const float*)(mpb + px*32);
                float4 wv = *(const float4*)mp;
                int4   ov = *(const int4*)(mp + 4);
                uint4 c00 = *(const uint4*)(xTb + (uint32_t)ov.x + cb);
                uint4 c01 = *(const uint4*)(xTb + (uint32_t)ov.y + cb);
                uint4 c10 = *(const uint4*)(xTb + (uint32_t)ov.z + cb);
                uint4 c11 = *(const uint4*)(xTb + (uint32_t)ov.w + cb);
                uint32_t outw[4];
                const uint32_t* u00 = &c00.x;
                const uint32_t* u01 = &c01.x;
                const uint32_t* u10 = &c10.x;
                const uint32_t* u11 = &c11.x;
                #pragma unroll
                for (int j = 0; j < 4; ++j) {
                    float2 f00 = __half22float2(*(const __half2*)&u00[j]);
                    float2 f01 = __half22float2(*(const __half2*)&u01[j]);
                    float2 f10 = __half22float2(*(const __half2*)&u10[j]);
                    float2 f11 = __half22float2(*(const __half2*)&u11[j]);
                    float lo = wv.x*f00.x + wv.y*f01.x + wv.z*f10.x + wv.w*f11.x;
                    float hi = wv.x*f00.y + wv.y*f01.y + wv.z*f10.y + wv.w*f11.y;
                    PACKH2(lo, hi, outw[j]);
                }
                uint32_t sw = sw128((uint32_t)(px*128 + ch4*16));
                *(uint4*)(sm + SM_A + sw) = make_uint4(outw[0],outw[1],outw[2],outw[3]);
            }
        }
        if (k < 8) META_FROM_SOM(k+1, (k+1)&1);

        if (k < 8) {
            uint32_t dst = smb + SM_W + ((k+1)&1)*16384u + tid*16;
            const char* src = g_Wsplit + (k+1)*16384 + tid*16;
            #pragma unroll
            for (int j = 0; j < 4; ++j) CP16(dst + j*4096u, src + j*4096);
            CP_COMMIT();
            CP_WAIT(1);
        } else {
            CP_WAIT(0);
        }
        __syncthreads();

        // tensor GEMM: per-ks fused 2 passes (A once, B hi + B lo)
        uint32_t wbase = smb + SM_W + (k & 1)*16384u;
        #pragma unroll
        for (int ks = 0; ks < 4; ++ks) {
            uint32_t ah[2][4], bh[2][4], bl[2][4];
            LDMATRIX_X4(ah[0][0],ah[0][1],ah[0][2],ah[0][3], smb + SM_A + aoff[0][ks]);
            LDMATRIX_X4(ah[1][0],ah[1][1],ah[1][2],ah[1][3], smb + SM_A + aoff[1][ks]);
            LDMATRIX_X4(bh[0][0],bh[0][1],bh[0][2],bh[0][3], wbase + boff[0][ks]);
            LDMATRIX_X4(bh[1][0],bh[1][1],bh[1][2],bh[1][3], wbase + boff[1][ks]);
            LDMATRIX_X4(bl[0][0],bl[0][1],bl[0][2],bl[0][3], wbase + 8192u + boff[0][ks]);
            LDMATRIX_X4(bl[1][0],bl[1][1],bl[1][2],bl[1][3], wbase + 8192u + boff[1][ks]);
            #pragma unroll
            for (int m = 0; m < 2; ++m)
                #pragma unroll
                for (int nt = 0; nt < 4; ++nt) {
                    int np = nt >> 1, bi = (nt & 1)*2;
                    MMA_FP16(acc[m][nt], ah[m][0],ah[m][1],ah[m][2],ah[m][3], bh[np][bi], bh[np][bi+1]);
                    MMA_FP16(acc[m][nt], ah[m][0],ah[m][1],ah[m][2],ah[m][3], bl[np][bi], bl[np][bi+1]);
                }
        }
    }

    // ---- epilogue: transpose via smem (reuse A+W region), coalesced store ----
    __syncthreads();
    float* ob = (float*)(sm + SM_A);   // pitch 132 floats, 33,792B fits in A+W (48KB)
    int g = l >> 2, tg = l & 3;
    #pragma unroll
    for (int m = 0; m < 2; ++m)
        #pragma unroll
        for (int nt = 0; nt < 4; ++nt) {
            int o  = o0 + nt*8 + 2*tg;
            int pa = px0 + m*16 + g;
            ob[o*132 + pa]         = acc[m][nt][0];
            ob[(o+1)*132 + pa]     = acc[m][nt][1];
            ob[o*132 + pa + 8]     = acc[m][nt][2];
            ob[(o+1)*132 + pa + 8] = acc[m][nt][3];
        }
    __syncthreads();
    for (int i = tid; i < 64*32; i += 256) {
        int o = i >> 5, seg = i & 31;
        float4 v = *(float4*)&ob[o*132 + seg*4];
        *(float4*)&out[(((size_t)b*CO + o)*HO + ho)*WO + seg*4] = v;
    }
}

// ---------------------------------------------------------------------------
extern "C" void kernel_launch(void* const* d_in, const int* in_sizes, int n_in,
                              void* d_out, int out_size) {
    const float* x      = (const float*)d_in[0];
    const float* w_off  = (const float*)d_in[1];
    const float* b_off  = (const float*)d_in[2];
    const float* w_mask = (const float*)d_in[3];
    const float* b_mask = (const float*)d_in[4];
    const float* w_conv = (const float*)d_in[5];
    float* out = (float*)d_out;

    prep_kernel<<<144, 256>>>(w_off, b_off, w_mask, b_mask, w_conv);
    transpose_kernel<<<dim3(4, 128, 8), 256>>>(x);

    cudaFuncSetAttribute((const void*)deform_kernel,
                         cudaFuncAttributeMaxDynamicSharedMemorySize, SM_TOTAL);
    deform_kernel<<<dim3(HO, B_), 256, SM_TOTAL>>>(out);
}

// round 14
// speedup vs baseline: 2.0168x; 1.1017x over previous
#include <cuda_runtime.h>
#include <cuda_fp16.h>
#include <math.h>
#include <stdint.h>

#define B_  8
#define CIN 64
#define H_  128
#define W_  128
#define HO  64
#define WO  128
#define CO  64
#define HW_ (H_*W_)

// Scratch (no allocations allowed -> __device__ globals)
__device__ float g_bias[32];
__device__ __align__(16) char g_Wsplit[9*16384];   // deform W: per tap fp16 hi 8KB + lo 8KB, SW128
__device__ __align__(16) char g_WomSplit[9*8192];  // conv W: per tap fp16 hi 4KB + lo 4KB, SW128
__device__ __align__(16) __half g_xT[(size_t)B_*H_*W_*CIN];  // NHWC fp16 x (16MB)

__device__ __forceinline__ uint32_t smem_u32(const void* p) {
    uint32_t a;
    asm("{ .reg .u64 t; cvta.to.shared.u64 t, %1; cvt.u32.u64 %0, t; }" : "=r"(a) : "l"(p));
    return a;
}
__device__ __forceinline__ uint32_t sw128(uint32_t off) { return off ^ ((off >> 3) & 0x70); }

#define LDMATRIX_X4(r0,r1,r2,r3,addr) \
    asm volatile("ldmatrix.sync.aligned.m8n8.x4.shared.b16 {%0,%1,%2,%3}, [%4];" \
                 : "=r"(r0),"=r"(r1),"=r"(r2),"=r"(r3) : "r"(addr))

#define MMA_FP16(c, a0,a1,a2,a3, b0,b1) \
    asm volatile("mma.sync.aligned.m16n8k16.row.col.f32.f16.f16.f32 " \
                 "{%0,%1,%2,%3},{%4,%5,%6,%7},{%8,%9},{%0,%1,%2,%3};" \
                 : "+f"((c)[0]),"+f"((c)[1]),"+f"((c)[2]),"+f"((c)[3]) \
                 : "r"(a0),"r"(a1),"r"(a2),"r"(a3), "r"(b0),"r"(b1))

#define CP16(dst, src) \
    asm volatile("cp.async.cg.shared.global [%0], [%1], 16;" :: "r"(dst), "l"(src) : "memory")
#define CP16Z(dst, src, sz) \
    asm volatile("cp.async.cg.shared.global [%0], [%1], 16, %2;" :: "r"(dst), "l"(src), "r"(sz) : "memory")
#define CP_COMMIT() asm volatile("cp.async.commit_group;" ::: "memory")
#define CP_WAIT(n)  asm volatile("cp.async.wait_group %0;" :: "n"(n) : "memory")

// pack (v0, v1) -> fp16x2 word (v1 high, v0 low)
#define PACKH2(v0, v1, h) \
    asm("cvt.rn.f16x2.f32 %0, %1, %2;" : "=r"(h) : "f"(v1), "f"(v0))

// ---------------------------------------------------------------------------
// Kernel 0: weight repack (fp16 hi/lo split, SW128 swizzled)
// ---------------------------------------------------------------------------
__global__ void prep_kernel(const float* __restrict__ w_off, const float* __restrict__ b_off,
                            const float* __restrict__ w_mask, const float* __restrict__ b_mask,
                            const float* __restrict__ w_conv) {
    int idx = blockIdx.x * blockDim.x + threadIdx.x;
    if (idx < 9*64*64) {
        int k = idx / 4096; int r = idx & 4095; int o = r >> 6; int c = r & 63;
        float w = w_conv[(o*64 + c)*9 + k];
        __half hi = __float2half(w);
        __half lo = __float2half(w - __half2float(hi));
        uint32_t sw = sw128((uint32_t)(o*128 + c*2));
        *(__half*)(g_Wsplit + k*16384 + sw)        = hi;
        *(__half*)(g_Wsplit + k*16384 + 8192 + sw) = lo;   // kept (unused in phase 2 now)
    }
    if (idx < 9*32*64) {
        int k = idx / 2048; int r = idx & 2047; int o = r >> 6; int c = r & 63;
        float w = 0.f;
        if (o < 18)       w = w_off[(o*64 + c)*9 + k];
        else if (o < 27)  w = w_mask[((o-18)*64 + c)*9 + k];
        __half hi = __float2half(w);
        __half lo = __float2half(w - __half2float(hi));
        uint32_t sw = sw128((uint32_t)(o*128 + c*2));
        *(__half*)(g_WomSplit + k*8192 + sw)        = hi;
        *(__half*)(g_WomSplit + k*8192 + 4096 + sw) = lo;
    }
    if (idx < 32) {
        float v = 0.f;
        if (idx < 18)      v = b_off[idx];
        else if (idx < 27) v = b_mask[idx - 18];
        g_bias[idx] = v;
    }
}

// ---------------------------------------------------------------------------
// Kernel 0b: NCHW fp32 -> NHWC fp16 transpose of x
// ---------------------------------------------------------------------------
__global__ void __launch_bounds__(256) transpose_kernel(const float* __restrict__ x) {
    __shared__ float t[64][33];
    int x0 = blockIdx.x * 32, y = blockIdx.y, b = blockIdx.z;
    int tx = threadIdx.x & 31, tc = threadIdx.x >> 5;
    const float* xb = x + (size_t)b * CIN * HW_ + y*W_ + x0;
    #pragma unroll
    for (int cc = 0; cc < 8; ++cc)
        t[tc + cc*8][tx] = __ldg(xb + (size_t)(tc + cc*8)*HW_ + tx);
    __syncthreads();
    __half* dst = g_xT + ((size_t)b*HW_ + y*W_ + x0) * CIN;
    int c2 = (threadIdx.x & 31) * 2;     // channel pair
    int xx = threadIdx.x >> 5;           // 0..7
    #pragma unroll
    for (int q = 0; q < 4; ++q) {
        int xp = xx + q*8;
        __half2 hv = __floats2half2_rn(t[c2][xp], t[c2+1][xp]);
        *(__half2*)(dst + (size_t)xp*CIN + c2) = hv;
    }
}

// ---------------------------------------------------------------------------
// Fused kernel: 128px x 64o per CTA, phase-2 B single-pass (hi only).
// ---------------------------------------------------------------------------
#define SM_A     0          // A fp16: 16KB, row px (128B, sw128)
#define SM_W     16384      // W double buffer: 2 x hi 8KB
#define SM_WOM   32768      // conv W double buffer: 2 x (hi 4KB + lo 4KB)
#define SM_META  49152      // meta double buffer: 2 x 128px x 32B
#define SM_SOM   57344      // som[128 px][33 floats] = 16,896B
#define SM_TOTAL 74240      // -> 2 CTAs/SM

__global__ void __launch_bounds__(256, 2) deform_kernel(float* __restrict__ out) {
    extern __shared__ char sm[];
    const uint32_t smb = smem_u32(sm);
    int tid = threadIdx.x;
    int l = tid & 31, w = tid >> 5;
    int ho = blockIdx.x, b = blockIdx.y;

    int px0 = (w & 3) * 32;          // mma px tile base
    int o0  = (w >> 2) * 32;         // phase-2 mma o tile base
    int oh  = (w >> 2) * 16;         // phase-1 o tile base
    int w16 = w * 16;                // gather px base (16 px per warp)
    int sub = l >> 3;                // px within 4-group
    int ch4 = l & 7;                 // 16B chunk within 128B row

    const char* xTb = (const char*)(g_xT + (size_t)b * HW_ * CIN);

    // ---- ldmatrix lane offsets (per-ks, sw128 wraps full offset) ----
    uint32_t aoff[2][4], boff[2][4], b1off[4];
    {
        int arow = px0 + (l & 15);
        int acol = (l & 16) ? 16 : 0;
        #pragma unroll
        for (int m = 0; m < 2; ++m)
            #pragma unroll
            for (int ks = 0; ks < 4; ++ks)
                aoff[m][ks] = sw128((uint32_t)((arow + m*16)*128 + ks*32 + acol));
        int brow = o0 + (l & 7) + ((l & 16) ? 8 : 0);
        int bcol = (l & 8) ? 16 : 0;
        #pragma unroll
        for (int np = 0; np < 2; ++np)
            #pragma unroll
            for (int ks = 0; ks < 4; ++ks)
                boff[np][ks] = sw128((uint32_t)((brow + np*16)*128 + ks*32 + bcol));
        int b1row = oh + (l & 7) + ((l & 16) ? 8 : 0);
        #pragma unroll
        for (int ks = 0; ks < 4; ++ks)
            b1off[ks] = sw128((uint32_t)(b1row*128 + ks*32 + bcol));
    }

    // ================= PHASE 1: offset/mask conv (128px x 32o) ================
    {
        uint32_t dst = smb + SM_WOM + tid*16;
        const char* src = g_WomSplit + tid*16;
        CP16(dst, src); CP16(dst + 4096u, src + 4096);
        CP_COMMIT();
    }

    float acc1[2][2][4];
    #pragma unroll
    for (int m = 0; m < 2; ++m)
        #pragma unroll
        for (int nt = 0; nt < 2; ++nt)
            #pragma unroll
            for (int r = 0; r < 4; ++r) acc1[m][nt][r] = 0.f;

    #pragma unroll 1
    for (int k = 0; k < 9; ++k) {
        if (k) __syncthreads();

        // A_k[px][c] = xT rows (im2col): pure cp.async copy, zero-fill at borders
        {
            int gy = 2*ho - 1 + (k/3);
            int gyc = max(gy, 0);
            #pragma unroll
            for (int it = 0; it < 4; ++it) {
                int px = w16 + it*4 + sub;
                int gx = px - 1 + (k%3);
                bool vld = (gy >= 0) && (gx >= 0) && (gx < W_);
                int gxc = min(max(gx, 0), W_-1);
                const char* src = xTb + ((size_t)(gyc*W_ + gxc)*128 + ch4*16);
                uint32_t dst = smb + SM_A + sw128((uint32_t)(px*128 + ch4*16));
                unsigned sz = vld ? 16u : 0u;
                CP16Z(dst, src, sz);
            }
            CP_COMMIT();
        }
        if (k < 8) {
            uint32_t dst = smb + SM_WOM + ((k+1)&1)*8192u + tid*16;
            const char* src = g_WomSplit + (k+1)*8192 + tid*16;
            CP16(dst, src); CP16(dst + 4096u, src + 4096);
            CP_COMMIT();
            CP_WAIT(1);    // A(k) + Wom(k) done; Wom(k+1) in flight
        } else {
            CP_WAIT(0);
        }
        __syncthreads();

        uint32_t wbase = smb + SM_WOM + (k & 1)*8192u;
        #pragma unroll
        for (int ks = 0; ks < 4; ++ks) {
            uint32_t ah[2][4], bh[4], bl[4];
            LDMATRIX_X4(ah[0][0],ah[0][1],ah[0][2],ah[0][3], smb + SM_A + aoff[0][ks]);
            LDMATRIX_X4(ah[1][0],ah[1][1],ah[1][2],ah[1][3], smb + SM_A + aoff[1][ks]);
            LDMATRIX_X4(bh[0],bh[1],bh[2],bh[3], wbase + b1off[ks]);
            LDMATRIX_X4(bl[0],bl[1],bl[2],bl[3], wbase + 4096u + b1off[ks]);
            #pragma unroll
            for (int m = 0; m < 2; ++m)
                #pragma unroll
                for (int nt = 0; nt < 2; ++nt) {
                    MMA_FP16(acc1[m][nt], ah[m][0],ah[m][1],ah[m][2],ah[m][3], bh[nt*2], bh[nt*2+1]);
                    MMA_FP16(acc1[m][nt], ah[m][0],ah[m][1],ah[m][2],ah[m][3], bl[nt*2], bl[nt*2+1]);
                }
        }
    }

    // write som[px][o] = acc + bias (pitch 33)
    {
        float* som = (float*)(sm + SM_SOM);
        int g = l >> 2, tg = l & 3;
        #pragma unroll
        for (int m = 0; m < 2; ++m)
            #pragma unroll
            for (int nt = 0; nt < 2; ++nt) {
                int o  = oh + nt*8 + 2*tg;
                int pa = px0 + m*16 + g;
                som[pa*33 + o]       = acc1[m][nt][0] + g_bias[o];
                som[pa*33 + o + 1]   = acc1[m][nt][1] + g_bias[o+1];
                som[(pa+8)*33 + o]   = acc1[m][nt][2] + g_bias[o];
                som[(pa+8)*33 + o+1] = acc1[m][nt][3] + g_bias[o+1];
            }
    }
    // stage deform W tap 0 (hi only)
    {
        uint32_t dst = smb + SM_W + tid*16;
        const char* src = g_Wsplit + tid*16;
        CP16(dst, src); CP16(dst + 4096u, src + 4096);
        CP_COMMIT();
    }
    __syncthreads();   // som visible

    // ================= PHASE 2: gather + deform GEMM =================
    #define META_FROM_SOM(TAP, BUF) do { \
        if (tid < 128) { \
            int px = tid; \
            const float* som = (const float*)(sm + SM_SOM); \
            float offy = som[px*33 + 2*(TAP)]; \
            float offx = som[px*33 + 2*(TAP) + 1]; \
            float mr   = som[px*33 + 18 + (TAP)]; \
            float mk   = 1.f / (1.f + expf(-mr)); \
            float py  = offy + (float)((TAP)/3) + (float)(2*ho - 1); \
            float pxx = offx + (float)((TAP)%3) + (float)(px - 1); \
            float y0f = floorf(py), x0f = floorf(pxx); \
            float dy = py - y0f,  dx = pxx - x0f; \
            int y0 = (int)y0f, x0 = (int)x0f; \
            int y1 = y0 + 1,   x1 = x0 + 1; \
            bool vy0 = (y0>=0)&&(y0<H_), vy1 = (y1>=0)&&(y1<H_); \
            bool vx0 = (x0>=0)&&(x0<W_), vx1 = (x1>=0)&&(x1<W_); \
            float* mp = (float*)(sm + SM_META + (BUF)*4096 + px*32); \
            mp[0] = (1.f-dy)*(1.f-dx)*mk * ((vy0&&vx0)?1.f:0.f); \
            mp[1] = (1.f-dy)*dx      *mk * ((vy0&&vx1)?1.f:0.f); \
            mp[2] = dy*(1.f-dx)      *mk * ((vy1&&vx0)?1.f:0.f); \
            mp[3] = dy*dx            *mk * ((vy1&&vx1)?1.f:0.f); \
            int cy0 = min(max(y0,0),H_-1), cy1 = min(max(y1,0),H_-1); \
            int cx0 = min(max(x0,0),W_-1), cx1 = min(max(x1,0),W_-1); \
            ((int*)mp)[4] = (cy0*W_ + cx0) << 7; \
            ((int*)mp)[5] = (cy0*W_ + cx1) << 7; \
            ((int*)mp)[6] = (cy1*W_ + cx0) << 7; \
            ((int*)mp)[7] = (cy1*W_ + cx1) << 7; \
        } \
    } while (0)

    META_FROM_SOM(0, 0);
    __syncthreads();

    float acc[2][4][4];
    #pragma unroll
    for (int m = 0; m < 2; ++m)
        #pragma unroll
        for (int nt = 0; nt < 4; ++nt)
            #pragma unroll
            for (int r = 0; r < 4; ++r) acc[m][nt][r] = 0.f;

    #pragma unroll 1
    for (int k = 0; k < 9; ++k) {
        if (k) __syncthreads();

        // gather tap k -> A. fp16 NHWC: LDG.128 = 4px x 1 corner x 8ch (full lines)
        {
            const char* mpb = sm + SM_META + (k & 1)*4096;
            uint32_t cb = (uint32_t)(ch4*16);
            #pragma unroll
            for (int it = 0; it < 4; ++it) {
                int px = w16 + it*4 + sub;
                const float* mp = (const float*)(mpb + px*32);
                float4 wv = *(const float4*)mp;
                int4   ov = *(const int4*)(mp + 4);
                uint4 c00 = *(const uint4*)(xTb + (uint32_t)ov.x + cb);
                uint4 c01 = *(const uint4*)(xTb + (uint32_t)ov.y + cb);
                uint4 c10 = *(const uint4*)(xTb + (uint32_t)ov.z + cb);
                uint4 c11 = *(const uint4*)(xTb + (uint32_t)ov.w + cb);
                uint32_t outw[4];
                const uint32_t* u00 = &c00.x;
                const uint32_t* u01 = &c01.x;
                const uint32_t* u10 = &c10.x;
                const uint32_t* u11 = &c11.x;
                #pragma unroll
                for (int j = 0; j < 4; ++j) {
                    float2 f00 = __half22float2(*(const __half2*)&u00[j]);
                    float2 f01 = __half22float2(*(const __half2*)&u01[j]);
                    float2 f10 = __half22float2(*(const __half2*)&u10[j]);
                    float2 f11 = __half22float2(*(const __half2*)&u11[j]);
                    float lo = wv.x*f00.x + wv.y*f01.x + wv.z*f10.x + wv.w*f11.x;
                    float hi = wv.x*f00.y + wv.y*f01.y + wv.z*f10.y + wv.w*f11.y;
                    PACKH2(lo, hi, outw[j]);
                }
                uint32_t sw = sw128((uint32_t)(px*128 + ch4*16));
                *(uint4*)(sm + SM_A + sw) = make_uint4(outw[0],outw[1],outw[2],outw[3]);
            }
        }
        if (k < 8) META_FROM_SOM(k+1, (k+1)&1);

        if (k < 8) {
            uint32_t dst = smb + SM_W + ((k+1)&1)*8192u + tid*16;
            const char* src = g_Wsplit + (k+1)*16384 + tid*16;
            CP16(dst, src); CP16(dst + 4096u, src + 4096);
            CP_COMMIT();
            CP_WAIT(1);
        } else {
            CP_WAIT(0);
        }
        __syncthreads();

        // tensor GEMM: single pass (B hi only)
        uint32_t wbase = smb + SM_W + (k & 1)*8192u;
        #pragma unroll
        for (int ks = 0; ks < 4; ++ks) {
            uint32_t ah[2][4], bh[2][4];
            LDMATRIX_X4(ah[0][0],ah[0][1],ah[0][2],ah[0][3], smb + SM_A + aoff[0][ks]);
            LDMATRIX_X4(ah[1][0],ah[1][1],ah[1][2],ah[1][3], smb + SM_A + aoff[1][ks]);
            LDMATRIX_X4(bh[0][0],bh[0][1],bh[0][2],bh[0][3], wbase + boff[0][ks]);
            LDMATRIX_X4(bh[1][0],bh[1][1],bh[1][2],bh[1][3], wbase + boff[1][ks]);
            #pragma unroll
            for (int m = 0; m < 2; ++m)
                #pragma unroll
                for (int nt = 0; nt < 4; ++nt) {
                    int np = nt >> 1, bi = (nt & 1)*2;
                    MMA_FP16(acc[m][nt], ah[m][0],ah[m][1],ah[m][2],ah[m][3], bh[np][bi], bh[np][bi+1]);
                }
        }
    }

    // ---- epilogue: transpose via smem (A+W+WOM region dead), coalesced store ----
    __syncthreads();
    float* ob = (float*)(sm + SM_A);   // pitch 132 floats, 33,792B < A+W+WOM (48KB)
    int g = l >> 2, tg = l & 3;
    #pragma unroll
    for (int m = 0; m < 2; ++m)
        #pragma unroll
        for (int nt = 0; nt < 4; ++nt) {
            int o  = o0 + nt*8 + 2*tg;
            int pa = px0 + m*16 + g;
            ob[o*132 + pa]         = acc[m][nt][0];
            ob[(o+1)*132 + pa]     = acc[m][nt][1];
            ob[o*132 + pa + 8]     = acc[m][nt][2];
            ob[(o+1)*132 + pa + 8] = acc[m][nt][3];
        }
    __syncthreads();
    for (int i = tid; i < 64*32; i += 256) {
        int o = i >> 5, seg = i & 31;
        float4 v = *(float4*)&ob[o*132 + seg*4];
        *(float4*)&out[(((size_t)b*CO + o)*HO + ho)*WO + seg*4] = v;
    }
}

// ---------------------------------------------------------------------------
extern "C" void kernel_launch(void* const* d_in, const int* in_sizes, int n_in,
                              void* d_out, int out_size) {
    const float* x      = (const float*)d_in[0];
    const float* w_off  = (const float*)d_in[1];
    const float* b_off  = (const float*)d_in[2];
    const float* w_mask = (const float*)d_in[3];
    const float* b_mask = (const float*)d_in[4];
    const float* w_conv = (const float*)d_in[5];
    float* out = (float*)d_out;

    prep_kernel<<<144, 256>>>(w_off, b_off, w_mask, b_mask, w_conv);
    transpose_kernel<<<dim3(4, 128, 8), 256>>>(x);

    cudaFuncSetAttribute((const void*)deform_kernel,
                         cudaFuncAttributeMaxDynamicSharedMemorySize, SM_TOTAL);
    deform_kernel<<<dim3(HO, B_), 256, SM_TOTAL>>>(out);
}

// round 16
// speedup vs baseline: 2.1346x; 1.0584x over previous
#include <cuda_runtime.h>
#include <cuda_fp16.h>
#include <math.h>
#include <stdint.h>

#define B_  8
#define CIN 64
#define H_  128
#define W_  128
#define HO  64
#define WO  128
#define CO  64
#define HW_ (H_*W_)

// Scratch (no allocations allowed -> __device__ globals)
__device__ float g_bias[32];
__device__ __align__(16) char g_Wsplit[9*16384];   // deform W: per tap fp16 hi 8KB (+lo slot unused)
__device__ __align__(16) char g_WomSplit[9*8192];  // conv W: per tap fp16 hi 4KB (+lo slot unused)
__device__ __align__(16) __half g_xT[(size_t)B_*H_*W_*CIN];  // NHWC fp16 x (16MB)

__device__ __forceinline__ uint32_t smem_u32(const void* p) {
    uint32_t a;
    asm("{ .reg .u64 t; cvta.to.shared.u64 t, %1; cvt.u32.u64 %0, t; }" : "=r"(a) : "l"(p));
    return a;
}
__device__ __forceinline__ uint32_t sw128(uint32_t off) { return off ^ ((off >> 3) & 0x70); }

#define LDMATRIX_X4(r0,r1,r2,r3,addr) \
    asm volatile("ldmatrix.sync.aligned.m8n8.x4.shared.b16 {%0,%1,%2,%3}, [%4];" \
                 : "=r"(r0),"=r"(r1),"=r"(r2),"=r"(r3) : "r"(addr))

#define MMA_FP16(c, a0,a1,a2,a3, b0,b1) \
    asm volatile("mma.sync.aligned.m16n8k16.row.col.f32.f16.f16.f32 " \
                 "{%0,%1,%2,%3},{%4,%5,%6,%7},{%8,%9},{%0,%1,%2,%3};" \
                 : "+f"((c)[0]),"+f"((c)[1]),"+f"((c)[2]),"+f"((c)[3]) \
                 : "r"(a0),"r"(a1),"r"(a2),"r"(a3), "r"(b0),"r"(b1))

#define CP16(dst, src) \
    asm volatile("cp.async.cg.shared.global [%0], [%1], 16;" :: "r"(dst), "l"(src) : "memory")
#define CP16Z(dst, src, sz) \
    asm volatile("cp.async.cg.shared.global [%0], [%1], 16, %2;" :: "r"(dst), "l"(src), "r"(sz) : "memory")
#define CP_COMMIT() asm volatile("cp.async.commit_group;" ::: "memory")
#define CP_WAIT(n)  asm volatile("cp.async.wait_group %0;" :: "n"(n) : "memory")

#define PACKH2(v0, v1, h) \
    asm("cvt.rn.f16x2.f32 %0, %1, %2;" : "=r"(h) : "f"(v1), "f"(v0))

// ---------------------------------------------------------------------------
// Kernel 0: weight repack (fp16, SW128 swizzled)
// ---------------------------------------------------------------------------
__global__ void prep_kernel(const float* __restrict__ w_off, const float* __restrict__ b_off,
                            const float* __restrict__ w_mask, const float* __restrict__ b_mask,
                            const float* __restrict__ w_conv) {
    int idx = blockIdx.x * blockDim.x + threadIdx.x;
    if (idx < 9*64*64) {
        int k = idx / 4096; int r = idx & 4095; int o = r >> 6; int c = r & 63;
        float w = w_conv[(o*64 + c)*9 + k];
        uint32_t sw = sw128((uint32_t)(o*128 + c*2));
        *(__half*)(g_Wsplit + k*16384 + sw) = __float2half(w);
    }
    if (idx < 9*32*64) {
        int k = idx / 2048; int r = idx & 2047; int o = r >> 6; int c = r & 63;
        float w = 0.f;
        if (o < 18)       w = w_off[(o*64 + c)*9 + k];
        else if (o < 27)  w = w_mask[((o-18)*64 + c)*9 + k];
        uint32_t sw = sw128((uint32_t)(o*128 + c*2));
        *(__half*)(g_WomSplit + k*8192 + sw) = __float2half(w);
    }
    if (idx < 32) {
        float v = 0.f;
        if (idx < 18)      v = b_off[idx];
        else if (idx < 27) v = b_mask[idx - 18];
        g_bias[idx] = v;
    }
}

// ---------------------------------------------------------------------------
// Kernel 0b: NCHW fp32 -> NHWC fp16 transpose of x
// ---------------------------------------------------------------------------
__global__ void __launch_bounds__(256) transpose_kernel(const float* __restrict__ x) {
    __shared__ float t[64][33];
    int x0 = blockIdx.x * 32, y = blockIdx.y, b = blockIdx.z;
    int tx = threadIdx.x & 31, tc = threadIdx.x >> 5;
    const float* xb = x + (size_t)b * CIN * HW_ + y*W_ + x0;
    #pragma unroll
    for (int cc = 0; cc < 8; ++cc)
        t[tc + cc*8][tx] = __ldg(xb + (size_t)(tc + cc*8)*HW_ + tx);
    __syncthreads();
    __half* dst = g_xT + ((size_t)b*HW_ + y*W_ + x0) * CIN;
    int c2 = (threadIdx.x & 31) * 2;
    int xx = threadIdx.x >> 5;
    #pragma unroll
    for (int q = 0; q < 4; ++q) {
        int xp = xx + q*8;
        __half2 hv = __floats2half2_rn(t[c2][xp], t[c2+1][xp]);
        *(__half2*)(dst + (size_t)xp*CIN + c2) = hv;
    }
}

// ---------------------------------------------------------------------------
// Fused kernel: 128px x 64o, double-buffered A, one sync per tap
// (order: build+commit -> CP_WAIT -> sync -> stage next W -> GEMM).
// ---------------------------------------------------------------------------
#define SM_A     0          // A fp16 double buffer: 2 x 16KB
#define SM_W     32768      // deform W hi double buffer: 2 x 8KB
#define SM_WOM   49152      // conv W hi double buffer: 2 x 4KB
#define SM_META  57344      // meta double buffer: 2 x 128px x 32B
#define SM_SOM   65536      // som[128 px][33 floats] = 16,896B
#define SM_TOTAL 82432      // -> 2 CTAs/SM

__global__ void __launch_bounds__(256, 2) deform_kernel(float* __restrict__ out) {
    extern __shared__ char sm[];
    const uint32_t smb = smem_u32(sm);
    int tid = threadIdx.x;
    int l = tid & 31, w = tid >> 5;
    int ho = blockIdx.x, b = blockIdx.y;

    int px0 = (w & 3) * 32;          // mma px tile base
    int o0  = (w >> 2) * 32;         // phase-2 mma o tile base
    int oh  = (w >> 2) * 16;         // phase-1 o tile base
    int w16 = w * 16;                // gather px base (16 px per warp)
    int sub = l >> 3;                // px within 4-group
    int ch4 = l & 7;                 // 16B chunk within 128B row

    const char* xTb = (const char*)(g_xT + (size_t)b * HW_ * CIN);

    // ---- ldmatrix lane offsets (per-ks, sw128 wraps full offset) ----
    uint32_t aoff[2][4], boff[2][4], b1off[4];
    {
        int arow = px0 + (l & 15);
        int acol = (l & 16) ? 16 : 0;
        #pragma unroll
        for (int m = 0; m < 2; ++m)
            #pragma unroll
            for (int ks = 0; ks < 4; ++ks)
                aoff[m][ks] = sw128((uint32_t)((arow + m*16)*128 + ks*32 + acol));
        int brow = o0 + (l & 7) + ((l & 16) ? 8 : 0);
        int bcol = (l & 8) ? 16 : 0;
        #pragma unroll
        for (int np = 0; np < 2; ++np)
            #pragma unroll
            for (int ks = 0; ks < 4; ++ks)
                boff[np][ks] = sw128((uint32_t)((brow + np*16)*128 + ks*32 + bcol));
        int b1row = oh + (l & 7) + ((l & 16) ? 8 : 0);
        #pragma unroll
        for (int ks = 0; ks < 4; ++ks)
            b1off[ks] = sw128((uint32_t)(b1row*128 + ks*32 + bcol));
    }

    // ================= PHASE 1: offset/mask conv (128px x 32o) ================
    // prologue: stage Wom(0) into WOM[0] (4KB)
    CP16(smb + SM_WOM + tid*16, g_WomSplit + tid*16);
    CP_COMMIT();

    float acc1[2][2][4];
    #pragma unroll
    for (int m = 0; m < 2; ++m)
        #pragma unroll
        for (int nt = 0; nt < 2; ++nt)
            #pragma unroll
            for (int r = 0; r < 4; ++r) acc1[m][nt][r] = 0.f;

    #pragma unroll 1
    for (int k = 0; k < 9; ++k) {
        uint32_t abase = smb + SM_A + (uint32_t)(k & 1)*16384u;
        // 1) build A(k) into A[k&1]: pure cp.async im2col copy, zero-fill at borders
        {
            int gy = 2*ho - 1 + (k/3);
            int gyc = max(gy, 0);
            #pragma unroll
            for (int it = 0; it < 4; ++it) {
                int px = w16 + it*4 + sub;
                int gx = px - 1 + (k%3);
                bool vld = (gy >= 0) && (gx >= 0) && (gx < W_);
                int gxc = min(max(gx, 0), W_-1);
                const char* src = xTb + ((size_t)(gyc*W_ + gxc)*128 + ch4*16);
                uint32_t dst = abase + sw128((uint32_t)(px*128 + ch4*16));
                CP16Z(dst, src, vld ? 16u : 0u);
            }
            CP_COMMIT();
        }
        // 2) own A(k) + Wom(k) complete
        CP_WAIT(0);
        // 3) everyone's copies visible; all warps past GEMM(k-1) -> WOM[(k+1)&1] free
        __syncthreads();
        // 4) stage Wom(k+1) (no wait; covered by next tap's CP_WAIT)
        if (k < 8) {
            CP16(smb + SM_WOM + ((k+1)&1)*4096u + tid*16, g_WomSplit + (k+1)*8192 + tid*16);
            CP_COMMIT();
        }
        // 5) GEMM(k)
        uint32_t wbase = smb + SM_WOM + (uint32_t)(k & 1)*4096u;
        #pragma unroll
        for (int ks = 0; ks < 4; ++ks) {
            uint32_t ah[2][4], bh[4];
            LDMATRIX_X4(ah[0][0],ah[0][1],ah[0][2],ah[0][3], abase + aoff[0][ks]);
            LDMATRIX_X4(ah[1][0],ah[1][1],ah[1][2],ah[1][3], abase + aoff[1][ks]);
            LDMATRIX_X4(bh[0],bh[1],bh[2],bh[3], wbase + b1off[ks]);
            #pragma unroll
            for (int m = 0; m < 2; ++m)
                #pragma unroll
                for (int nt = 0; nt < 2; ++nt)
                    MMA_FP16(acc1[m][nt], ah[m][0],ah[m][1],ah[m][2],ah[m][3], bh[nt*2], bh[nt*2+1]);
        }
    }
    __syncthreads();   // all GEMM(8) done before som/meta writes below

    // write som[px][o] = acc + bias (pitch 33)
    {
        float* som = (float*)(sm + SM_SOM);
        int g = l >> 2, tg = l & 3;
        #pragma unroll
        for (int m = 0; m < 2; ++m)
            #pragma unroll
            for (int nt = 0; nt < 2; ++nt) {
                int o  = oh + nt*8 + 2*tg;
                int pa = px0 + m*16 + g;
                som[pa*33 + o]       = acc1[m][nt][0] + g_bias[o];
                som[pa*33 + o + 1]   = acc1[m][nt][1] + g_bias[o+1];
                som[(pa+8)*33 + o]   = acc1[m][nt][2] + g_bias[o];
                som[(pa+8)*33 + o+1] = acc1[m][nt][3] + g_bias[o+1];
            }
    }
    // stage deform W tap 0 (hi, 8KB) — completion covered by phase-2 k=0 CP_WAIT
    {
        uint32_t dst = smb + SM_W + tid*16;
        const char* src = g_Wsplit + tid*16;
        CP16(dst, src); CP16(dst + 4096u, src + 4096);
        CP_COMMIT();
    }
    __syncthreads();   // som visible

    // ================= PHASE 2: gather + deform GEMM =================
    #define META_FROM_SOM(TAP, BUF) do { \
        if (tid < 128) { \
            int px = tid; \
            const float* som = (const float*)(sm + SM_SOM); \
            float offy = som[px*33 + 2*(TAP)]; \
            float offx = som[px*33 + 2*(TAP) + 1]; \
            float mr   = som[px*33 + 18 + (TAP)]; \
            float mk   = 1.f / (1.f + expf(-mr)); \
            float py  = offy + (float)((TAP)/3) + (float)(2*ho - 1); \
            float pxx = offx + (float)((TAP)%3) + (float)(px - 1); \
            float y0f = floorf(py), x0f = floorf(pxx); \
            float dy = py - y0f,  dx = pxx - x0f; \
            int y0 = (int)y0f, x0 = (int)x0f; \
            int y1 = y0 + 1,   x1 = x0 + 1; \
            bool vy0 = (y0>=0)&&(y0<H_), vy1 = (y1>=0)&&(y1<H_); \
            bool vx0 = (x0>=0)&&(x0<W_), vx1 = (x1>=0)&&(x1<W_); \
            float* mp = (float*)(sm + SM_META + (BUF)*4096 + px*32); \
            mp[0] = (1.f-dy)*(1.f-dx)*mk * ((vy0&&vx0)?1.f:0.f); \
            mp[1] = (1.f-dy)*dx      *mk * ((vy0&&vx1)?1.f:0.f); \
            mp[2] = dy*(1.f-dx)      *mk * ((vy1&&vx0)?1.f:0.f); \
            mp[3] = dy*dx            *mk * ((vy1&&vx1)?1.f:0.f); \
            int cy0 = min(max(y0,0),H_-1), cy1 = min(max(y1,0),H_-1); \
            int cx0 = min(max(x0,0),W_-1), cx1 = min(max(x1,0),W_-1); \
            ((int*)mp)[4] = (cy0*W_ + cx0) << 7; \
            ((int*)mp)[5] = (cy0*W_ + cx1) << 7; \
            ((int*)mp)[6] = (cy1*W_ + cx0) << 7; \
            ((int*)mp)[7] = (cy1*W_ + cx1) << 7; \
        } \
    } while (0)

    META_FROM_SOM(0, 0);
    __syncthreads();   // meta(0) visible

    float acc[2][4][4];
    #pragma unroll
    for (int m = 0; m < 2; ++m)
        #pragma unroll
        for (int nt = 0; nt < 4; ++nt)
            #pragma unroll
            for (int r = 0; r < 4; ++r) acc[m][nt][r] = 0.f;

    #pragma unroll 1
    for (int k = 0; k < 9; ++k) {
        uint32_t abase = smb + SM_A + (uint32_t)(k & 1)*16384u;
        // 1) gather tap k -> A[k&1] via STS (fp16 NHWC: LDG.128 = 4px x 1 corner x 8ch)
        {
            const char* mpb = sm + SM_META + (k & 1)*4096;
            uint32_t cb = (uint32_t)(ch4*16);
            #pragma unroll
            for (int it = 0; it < 4; ++it) {
                int px = w16 + it*4 + sub;
                const float* mp = (const float*)(mpb + px*32);
                float4 wv = *(const float4*)mp;
                int4   ov = *(const int4*)(mp + 4);
                uint4 c00 = *(const uint4*)(xTb + (uint32_t)ov.x + cb);
                uint4 c01 = *(const uint4*)(xTb + (uint32_t)ov.y + cb);
                uint4 c10 = *(const uint4*)(xTb + (uint32_t)ov.z + cb);
                uint4 c11 = *(const uint4*)(xTb + (uint32_t)ov.w + cb);
                uint32_t outw[4];
                const uint32_t* u00 = &c00.x;
                const uint32_t* u01 = &c01.x;
                const uint32_t* u10 = &c10.x;
                const uint32_t* u11 = &c11.x;
                #pragma unroll
                for (int j = 0; j < 4; ++j) {
                    float2 f00 = __half22float2(*(const __half2*)&u00[j]);
                    float2 f01 = __half22float2(*(const __half2*)&u01[j]);
                    float2 f10 = __half22float2(*(const __half2*)&u10[j]);
                    float2 f11 = __half22float2(*(const __half2*)&u11[j]);
                    float lo = wv.x*f00.x + wv.y*f01.x + wv.z*f10.x + wv.w*f11.x;
                    float hi = wv.x*f00.y + wv.y*f01.y + wv.z*f10.y + wv.w*f11.y;
                    PACKH2(lo, hi, outw[j]);
                }
                uint32_t sw = sw128((uint32_t)(px*128 + ch4*16));
                *(uint4*)(sm + SM_A + (k & 1)*16384 + sw) = make_uint4(outw[0],outw[1],outw[2],outw[3]);
            }
        }
        if (k < 8) META_FROM_SOM(k+1, (k+1)&1);
        // 2) own W(k) copies complete (issued a full tap ago)
        CP_WAIT(0);
        // 3) STS/meta visible; all warps past GEMM(k-1) -> W[(k+1)&1] free
        __syncthreads();
        // 4) stage Wd(k+1) (no wait)
        if (k < 8) {
            uint32_t dst = smb + SM_W + ((k+1)&1)*8192u + tid*16;
            const char* src = g_Wsplit + (k+1)*16384 + tid*16;
            CP16(dst, src); CP16(dst + 4096u, src + 4096);
            CP_COMMIT();
        }
        // 5) GEMM(k): single pass (B hi)
        uint32_t wbase = smb + SM_W + (uint32_t)(k & 1)*8192u;
        #pragma unroll
        for (int ks = 0; ks < 4; ++ks) {
            uint32_t ah[2][4], bh[2][4];
            LDMATRIX_X4(ah[0][0],ah[0][1],ah[0][2],ah[0][3], abase + aoff[0][ks]);
            LDMATRIX_X4(ah[1][0],ah[1][1],ah[1][2],ah[1][3], abase + aoff[1][ks]);
            LDMATRIX_X4(bh[0][0],bh[0][1],bh[0][2],bh[0][3], wbase + boff[0][ks]);
            LDMATRIX_X4(bh[1][0],bh[1][1],bh[1][2],bh[1][3], wbase + boff[1][ks]);
            #pragma unroll
            for (int m = 0; m < 2; ++m)
                #pragma unroll
                for (int nt = 0; nt < 4; ++nt) {
                    int np = nt >> 1, bi = (nt & 1)*2;
                    MMA_FP16(acc[m][nt], ah[m][0],ah[m][1],ah[m][2],ah[m][3], bh[np][bi], bh[np][bi+1]);
                }
        }
    }

    // ---- epilogue: transpose via smem (A/W dead), coalesced store ----
    __syncthreads();
    float* ob = (float*)(sm + SM_A);   // pitch 132 floats, 33,792B < A region
    int g = l >> 2, tg = l & 3;
    #pragma unroll
    for (int m = 0; m < 2; ++m)
        #pragma unroll
        for (int nt = 0; nt < 4; ++nt) {
            int o  = o0 + nt*8 + 2*tg;
            int pa = px0 + m*16 + g;
            ob[o*132 + pa]         = acc[m][nt][0];
            ob[(o+1)*132 + pa]     = acc[m][nt][1];
            ob[o*132 + pa + 8]     = acc[m][nt][2];
            ob[(o+1)*132 + pa + 8] = acc[m][nt][3];
        }
    __syncthreads();
    for (int i = tid; i < 64*32; i += 256) {
        int o = i >> 5, seg = i & 31;
        float4 v = *(float4*)&ob[o*132 + seg*4];
        *(float4*)&out[(((size_t)b*CO + o)*HO + ho)*WO + seg*4] = v;
    }
}

// ---------------------------------------------------------------------------
extern "C" void kernel_launch(void* const* d_in, const int* in_sizes, int n_in,
                              void* d_out, int out_size) {
    const float* x      = (const float*)d_in[0];
    const float* w_off  = (const float*)d_in[1];
    const float* b_off  = (const float*)d_in[2];
    const float* w_mask = (const float*)d_in[3];
    const float* b_mask = (const float*)d_in[4];
    const float* w_conv = (const float*)d_in[5];
    float* out = (float*)d_out;

    prep_kernel<<<144, 256>>>(w_off, b_off, w_mask, b_mask, w_conv);
    transpose_kernel<<<dim3(4, 128, 8), 256>>>(x);

    cudaFuncSetAttribute((const void*)deform_kernel,
                         cudaFuncAttributeMaxDynamicSharedMemorySize, SM_TOTAL);
    deform_kernel<<<dim3(HO, B_), 256, SM_TOTAL>>>(out);
}

// round 17
// speedup vs baseline: 2.2681x; 1.0625x over previous
#include <cuda_runtime.h>
#include <cuda_fp16.h>
#include <math.h>
#include <stdint.h>

#define B_  8
#define CIN 64
#define H_  128
#define W_  128
#define HO  64
#define WO  128
#define CO  64
#define HW_ (H_*W_)

// Scratch (no allocations allowed -> __device__ globals)
__device__ float g_bias[32];
__device__ __align__(16) char g_Wsplit[9*16384];   // deform W: per tap fp16 hi 8KB (+lo slot unused)
__device__ __align__(16) char g_WomSplit[9*8192];  // conv W: per tap fp16 hi 4KB (+lo slot unused)
__device__ __align__(16) __half g_xT[(size_t)B_*H_*W_*CIN];  // NHWC fp16 x (16MB)

__device__ __forceinline__ uint32_t smem_u32(const void* p) {
    uint32_t a;
    asm("{ .reg .u64 t; cvta.to.shared.u64 t, %1; cvt.u32.u64 %0, t; }" : "=r"(a) : "l"(p));
    return a;
}
__device__ __forceinline__ uint32_t sw128(uint32_t off) { return off ^ ((off >> 3) & 0x70); }

#define LDMATRIX_X4(r0,r1,r2,r3,addr) \
    asm volatile("ldmatrix.sync.aligned.m8n8.x4.shared.b16 {%0,%1,%2,%3}, [%4];" \
                 : "=r"(r0),"=r"(r1),"=r"(r2),"=r"(r3) : "r"(addr))

#define MMA_FP16(c, a0,a1,a2,a3, b0,b1) \
    asm volatile("mma.sync.aligned.m16n8k16.row.col.f32.f16.f16.f32 " \
                 "{%0,%1,%2,%3},{%4,%5,%6,%7},{%8,%9},{%0,%1,%2,%3};" \
                 : "+f"((c)[0]),"+f"((c)[1]),"+f"((c)[2]),"+f"((c)[3]) \
                 : "r"(a0),"r"(a1),"r"(a2),"r"(a3), "r"(b0),"r"(b1))

#define CP16(dst, src) \
    asm volatile("cp.async.cg.shared.global [%0], [%1], 16;" :: "r"(dst), "l"(src) : "memory")
#define CP16Z(dst, src, sz) \
    asm volatile("cp.async.cg.shared.global [%0], [%1], 16, %2;" :: "r"(dst), "l"(src), "r"(sz) : "memory")
#define CP_COMMIT() asm volatile("cp.async.commit_group;" ::: "memory")
#define CP_WAIT(n)  asm volatile("cp.async.wait_group %0;" :: "n"(n) : "memory")

#define PACKH2(v0, v1, h) \
    asm("cvt.rn.f16x2.f32 %0, %1, %2;" : "=r"(h) : "f"(v1), "f"(v0))

// ---------------------------------------------------------------------------
// Kernel 0: NCHW fp32 -> NHWC fp16 transpose; first 144 blocks also repack W.
// ---------------------------------------------------------------------------
__global__ void __launch_bounds__(256) transprep_kernel(
        const float* __restrict__ x,
        const float* __restrict__ w_off, const float* __restrict__ b_off,
        const float* __restrict__ w_mask, const float* __restrict__ b_mask,
        const float* __restrict__ w_conv) {
    __shared__ float t[64][33];
    int x0 = blockIdx.x * 32, y = blockIdx.y, b = blockIdx.z;
    int tx = threadIdx.x & 31, tc = threadIdx.x >> 5;
    const float* xb = x + (size_t)b * CIN * HW_ + y*W_ + x0;
    #pragma unroll
    for (int cc = 0; cc < 8; ++cc)
        t[tc + cc*8][tx] = __ldg(xb + (size_t)(tc + cc*8)*HW_ + tx);

    // weight repack on the first 144 flat blocks (independent data)
    int flat = (blockIdx.z * gridDim.y + blockIdx.y) * gridDim.x + blockIdx.x;
    if (flat < 144) {
        int idx = flat * 256 + threadIdx.x;
        if (idx < 9*64*64) {
            int k = idx / 4096; int r = idx & 4095; int o = r >> 6; int c = r & 63;
            float w = w_conv[(o*64 + c)*9 + k];
            uint32_t sw = sw128((uint32_t)(o*128 + c*2));
            *(__half*)(g_Wsplit + k*16384 + sw) = __float2half(w);
        }
        if (idx < 9*32*64) {
            int k = idx / 2048; int r = idx & 2047; int o = r >> 6; int c = r & 63;
            float w = 0.f;
            if (o < 18)       w = w_off[(o*64 + c)*9 + k];
            else if (o < 27)  w = w_mask[((o-18)*64 + c)*9 + k];
            uint32_t sw = sw128((uint32_t)(o*128 + c*2));
            *(__half*)(g_WomSplit + k*8192 + sw) = __float2half(w);
        }
        if (idx < 32) {
            float v = 0.f;
            if (idx < 18)      v = b_off[idx];
            else if (idx < 27) v = b_mask[idx - 18];
            g_bias[idx] = v;
        }
    }

    __syncthreads();
    __half* dst = g_xT + ((size_t)b*HW_ + y*W_ + x0) * CIN;
    int c2 = (threadIdx.x & 31) * 2;
    int xx = threadIdx.x >> 5;
    #pragma unroll
    for (int q = 0; q < 4; ++q) {
        int xp = xx + q*8;
        __half2 hv = __floats2half2_rn(t[c2][xp], t[c2+1][xp]);
        *(__half2*)(dst + (size_t)xp*CIN + c2) = hv;
    }
}

// ---------------------------------------------------------------------------
// Fused kernel: phase 1 reads A straight from a bordered row buffer (XR),
// zero per-tap staging / zero syncs in phase 1. Phase 2 as R16.
// ---------------------------------------------------------------------------
#define SM_XR    0          // 390 rows x 128B = 49,920B (phase2: A dbl 32K + Wd dbl 16K)
#define SM_WOM9  50176      // 9 x 4KB Wom tiles (phase2 overlays META dbl here)
#define SM_META  50176
#define SM_SOM   87040      // som[128 px][33 floats] = 16,896B
#define SM_TOTAL 103936     // -> 2 CTAs/SM

__global__ void __launch_bounds__(256, 2) deform_kernel(float* __restrict__ out) {
    extern __shared__ char sm[];
    const uint32_t smb = smem_u32(sm);
    int tid = threadIdx.x;
    int l = tid & 31, w = tid >> 5;
    int ho = blockIdx.x, b = blockIdx.y;

    int px0 = (w & 3) * 32;          // mma px tile base
    int o0  = (w >> 2) * 32;         // phase-2 mma o tile base
    int oh  = (w >> 2) * 16;         // phase-1 o tile base
    int w16 = w * 16;                // gather px base (16 px per warp)
    int sub = l >> 3;                // px within 4-group
    int ch4 = l & 7;                 // 16B chunk within 128B row

    const char* xTb = (const char*)(g_xT + (size_t)b * HW_ * CIN);

    // ---- ldmatrix lane offsets ----
    uint32_t aoff[2][4], boff[2][4], b1off[4], a1base[2][4];
    {
        int arow = px0 + (l & 15);
        int acol = (l & 16) ? 16 : 0;
        #pragma unroll
        for (int m = 0; m < 2; ++m)
            #pragma unroll
            for (int ks = 0; ks < 4; ++ks) {
                aoff[m][ks]   = sw128((uint32_t)((arow + m*16)*128 + ks*32 + acol));
                a1base[m][ks] = (uint32_t)((arow + m*16)*128 + ks*32 + acol);  // un-swizzled
            }
        int brow = o0 + (l & 7) + ((l & 16) ? 8 : 0);
        int bcol = (l & 8) ? 16 : 0;
        #pragma unroll
        for (int np = 0; np < 2; ++np)
            #pragma unroll
            for (int ks = 0; ks < 4; ++ks)
                boff[np][ks] = sw128((uint32_t)((brow + np*16)*128 + ks*32 + bcol));
        int b1row = oh + (l & 7) + ((l & 16) ? 8 : 0);
        #pragma unroll
        for (int ks = 0; ks < 4; ++ks)
            b1off[ks] = sw128((uint32_t)(b1row*128 + ks*32 + bcol));
    }

    // ================= PROLOGUE: stage XR rows + all 9 Wom tiles ==============
    // XR: rows r = y*130 + x, y in {0,1,2} -> gy = 2ho-1+y, x in [0,129] -> gx = x-1
    for (int t = tid; t < 390*8; t += 256) {
        int r = t >> 3, ch = t & 7;
        int yy = r / 130, xx = r % 130;
        int gy = 2*ho - 1 + yy;
        int gx = xx - 1;
        bool vld = (gy >= 0) && (gx >= 0) && (gx < W_);
        const char* src = xTb + (((size_t)(max(gy,0)*W_ + min(max(gx,0), W_-1))) << 7) + ch*16;
        uint32_t dst = smb + SM_XR + sw128((uint32_t)(r*128 + ch*16));
        CP16Z(dst, src, vld ? 16u : 0u);
    }
    for (int t = tid; t < 9*256; t += 256) {
        int tap = t >> 8, j = t & 255;
        CP16(smb + SM_WOM9 + (uint32_t)tap*4096u + j*16, g_WomSplit + tap*8192 + j*16);
    }
    CP_COMMIT();
    CP_WAIT(0);
    __syncthreads();

    // ================= PHASE 1: offset/mask conv — pure compute ==============
    float acc1[2][2][4];
    #pragma unroll
    for (int m = 0; m < 2; ++m)
        #pragma unroll
        for (int nt = 0; nt < 2; ++nt)
            #pragma unroll
            for (int r = 0; r < 4; ++r) acc1[m][nt][r] = 0.f;

    #pragma unroll 1
    for (int k = 0; k < 9; ++k) {
        uint32_t radd  = (uint32_t)(((k/3)*130 + (k%3)) * 128);
        uint32_t wbase = smb + SM_WOM9 + (uint32_t)k*4096u;
        #pragma unroll
        for (int ks = 0; ks < 4; ++ks) {
            uint32_t ah[2][4], bh[4];
            LDMATRIX_X4(ah[0][0],ah[0][1],ah[0][2],ah[0][3], smb + SM_XR + sw128(a1base[0][ks] + radd));
            LDMATRIX_X4(ah[1][0],ah[1][1],ah[1][2],ah[1][3], smb + SM_XR + sw128(a1base[1][ks] + radd));
            LDMATRIX_X4(bh[0],bh[1],bh[2],bh[3], wbase + b1off[ks]);
            #pragma unroll
            for (int m = 0; m < 2; ++m)
                #pragma unroll
                for (int nt = 0; nt < 2; ++nt)
                    MMA_FP16(acc1[m][nt], ah[m][0],ah[m][1],ah[m][2],ah[m][3], bh[nt*2], bh[nt*2+1]);
        }
    }
    __syncthreads();   // all XR / WOM9 reads done -> regions reusable

    // write som[px][o] = acc + bias (pitch 33)
    {
        float* som = (float*)(sm + SM_SOM);
        int g = l >> 2, tg = l & 3;
        #pragma unroll
        for (int m = 0; m < 2; ++m)
            #pragma unroll
            for (int nt = 0; nt < 2; ++nt) {
                int o  = oh + nt*8 + 2*tg;
                int pa = px0 + m*16 + g;
                som[pa*33 + o]       = acc1[m][nt][0] + g_bias[o];
                som[pa*33 + o + 1]   = acc1[m][nt][1] + g_bias[o+1];
                som[(pa+8)*33 + o]   = acc1[m][nt][2] + g_bias[o];
                som[(pa+8)*33 + o+1] = acc1[m][nt][3] + g_bias[o+1];
            }
    }
    // stage deform W tap 0 (hi, 8KB) into XR+32K — completion via phase-2 k=0 CP_WAIT
    {
        uint32_t dst = smb + SM_XR + 32768u + tid*16;
        const char* src = g_Wsplit + tid*16;
        CP16(dst, src); CP16(dst + 4096u, src + 4096);
        CP_COMMIT();
    }
    __syncthreads();   // som visible

    // ================= PHASE 2: gather + deform GEMM =================
    #define META_FROM_SOM(TAP, BUF) do { \
        if (tid < 128) { \
            int px = tid; \
            const float* som = (const float*)(sm + SM_SOM); \
            float offy = som[px*33 + 2*(TAP)]; \
            float offx = som[px*33 + 2*(TAP) + 1]; \
            float mr   = som[px*33 + 18 + (TAP)]; \
            float mk   = 1.f / (1.f + expf(-mr)); \
            float py  = offy + (float)((TAP)/3) + (float)(2*ho - 1); \
            float pxx = offx + (float)((TAP)%3) + (float)(px - 1); \
            float y0f = floorf(py), x0f = floorf(pxx); \
            float dy = py - y0f,  dx = pxx - x0f; \
            int y0 = (int)y0f, x0 = (int)x0f; \
            int y1 = y0 + 1,   x1 = x0 + 1; \
            bool vy0 = (y0>=0)&&(y0<H_), vy1 = (y1>=0)&&(y1<H_); \
            bool vx0 = (x0>=0)&&(x0<W_), vx1 = (x1>=0)&&(x1<W_); \
            float* mp = (float*)(sm + SM_META + (BUF)*4096 + px*32); \
            mp[0] = (1.f-dy)*(1.f-dx)*mk * ((vy0&&vx0)?1.f:0.f); \
            mp[1] = (1.f-dy)*dx      *mk * ((vy0&&vx1)?1.f:0.f); \
            mp[2] = dy*(1.f-dx)      *mk * ((vy1&&vx0)?1.f:0.f); \
            mp[3] = dy*dx            *mk * ((vy1&&vx1)?1.f:0.f); \
            int cy0 = min(max(y0,0),H_-1), cy1 = min(max(y1,0),H_-1); \
            int cx0 = min(max(x0,0),W_-1), cx1 = min(max(x1,0),W_-1); \
            ((int*)mp)[4] = (cy0*W_ + cx0) << 7; \
            ((int*)mp)[5] = (cy0*W_ + cx1) << 7; \
            ((int*)mp)[6] = (cy1*W_ + cx0) << 7; \
            ((int*)mp)[7] = (cy1*W_ + cx1) << 7; \
        } \
    } while (0)

    META_FROM_SOM(0, 0);
    __syncthreads();   // meta(0) visible

    float acc[2][4][4];
    #pragma unroll
    for (int m = 0; m < 2; ++m)
        #pragma unroll
        for (int nt = 0; nt < 4; ++nt)
            #pragma unroll
            for (int r = 0; r < 4; ++r) acc[m][nt][r] = 0.f;

    #pragma unroll 1
    for (int k = 0; k < 9; ++k) {
        uint32_t abase = smb + SM_XR + (uint32_t)(k & 1)*16384u;
        // 1) gather tap k -> A[k&1] via STS (fp16 NHWC: LDG.128 = 4px x 1 corner x 8ch)
        {
            const char* mpb = sm + SM_META + (k & 1)*4096;
            uint32_t cb = (uint32_t)(ch4*16);
            #pragma unroll
            for (int it = 0; it < 4; ++it) {
                int px = w16 + it*4 + sub;
                const float* mp = (const float*)(mpb + px*32);
                float4 wv = *(const float4*)mp;
                int4   ov = *(const int4*)(mp + 4);
                uint4 c00 = *(const uint4*)(xTb + (uint32_t)ov.x + cb);
                uint4 c01 = *(const uint4*)(xTb + (uint32_t)ov.y + cb);
                uint4 c10 = *(const uint4*)(xTb + (uint32_t)ov.z + cb);
                uint4 c11 = *(const uint4*)(xTb + (uint32_t)ov.w + cb);
                uint32_t outw[4];
                const uint32_t* u00 = &c00.x;
                const uint32_t* u01 = &c01.x;
                const uint32_t* u10 = &c10.x;
                const uint32_t* u11 = &c11.x;
                #pragma unroll
                for (int j = 0; j < 4; ++j) {
                    float2 f00 = __half22float2(*(const __half2*)&u00[j]);
                    float2 f01 = __half22float2(*(const __half2*)&u01[j]);
                    float2 f10 = __half22float2(*(const __half2*)&u10[j]);
                    float2 f11 = __half22float2(*(const __half2*)&u11[j]);
                    float lo = wv.x*f00.x + wv.y*f01.x + wv.z*f10.x + wv.w*f11.x;
                    float hi = wv.x*f00.y + wv.y*f01.y + wv.z*f10.y + wv.w*f11.y;
                    PACKH2(lo, hi, outw[j]);
                }
                uint32_t sw = sw128((uint32_t)(px*128 + ch4*16));
                *(uint4*)(sm + SM_XR + (k & 1)*16384 + sw) = make_uint4(outw[0],outw[1],outw[2],outw[3]);
            }
        }
        if (k < 8) META_FROM_SOM(k+1, (k+1)&1);
        // 2) own W(k) copies complete (issued a full tap ago)
        CP_WAIT(0);
        // 3) STS/meta visible; all warps past GEMM(k-1) -> W[(k+1)&1] free
        __syncthreads();
        // 4) stage Wd(k+1) (no wait)
        if (k < 8) {
            uint32_t dst = smb + SM_XR + 32768u + ((k+1)&1)*8192u + tid*16;
            const char* src = g_Wsplit + (k+1)*16384 + tid*16;
            CP16(dst, src); CP16(dst + 4096u, src + 4096);
            CP_COMMIT();
        }
        // 5) GEMM(k): single pass (B hi)
        uint32_t wbase = smb + SM_XR + 32768u + (uint32_t)(k & 1)*8192u;
        #pragma unroll
        for (int ks = 0; ks < 4; ++ks) {
            uint32_t ah[2][4], bh[2][4];
            LDMATRIX_X4(ah[0][0],ah[0][1],ah[0][2],ah[0][3], abase + aoff[0][ks]);
            LDMATRIX_X4(ah[1][0],ah[1][1],ah[1][2],ah[1][3], abase + aoff[1][ks]);
            LDMATRIX_X4(bh[0][0],bh[0][1],bh[0][2],bh[0][3], wbase + boff[0][ks]);
            LDMATRIX_X4(bh[1][0],bh[1][1],bh[1][2],bh[1][3], wbase + boff[1][ks]);
            #pragma unroll
            for (int m = 0; m < 2; ++m)
                #pragma unroll
                for (int nt = 0; nt < 4; ++nt) {
                    int np = nt >> 1, bi = (nt & 1)*2;
                    MMA_FP16(acc[m][nt], ah[m][0],ah[m][1],ah[m][2],ah[m][3], bh[np][bi], bh[np][bi+1]);
                }
        }
    }

    // ---- epilogue: transpose via smem (XR dead), coalesced store ----
    __syncthreads();
    float* ob = (float*)(sm + SM_XR);   // pitch 132 floats, 33,792B < XR
    int g = l >> 2, tg = l & 3;
    #pragma unroll
    for (int m = 0; m < 2; ++m)
        #pragma unroll
        for (int nt = 0; nt < 4; ++nt) {
            int o  = o0 + nt*8 + 2*tg;
            int pa = px0 + m*16 + g;
            ob[o*132 + pa]         = acc[m][nt][0];
            ob[(o+1)*132 + pa]     = acc[m][nt][1];
            ob[o*132 + pa + 8]     = acc[m][nt][2];
            ob[(o+1)*132 + pa + 8] = acc[m][nt][3];
        }
    __syncthreads();
    for (int i = tid; i < 64*32; i += 256) {
        int o = i >> 5, seg = i & 31;
        float4 v = *(float4*)&ob[o*132 + seg*4];
        *(float4*)&out[(((size_t)b*CO + o)*HO + ho)*WO + seg*4] = v;
    }
}

// ---------------------------------------------------------------------------
extern "C" void kernel_launch(void* const* d_in, const int* in_sizes, int n_in,
                              void* d_out, int out_size) {
    const float* x      = (const float*)d_in[0];
    const float* w_off  = (const float*)d_in[1];
    const float* b_off  = (const float*)d_in[2];
    const float* w_mask = (const float*)d_in[3];
    const float* b_mask = (const float*)d_in[4];
    const float* w_conv = (const float*)d_in[5];
    float* out = (float*)d_out;

    transprep_kernel<<<dim3(4, 128, 8), 256>>>(x, w_off, b_off, w_mask, b_mask, w_conv);

    cudaFuncSetAttribute((const void*)deform_kernel,
                         cudaFuncAttributeMaxDynamicSharedMemorySize, SM_TOTAL);
    deform_kernel<<<dim3(HO, B_), 256, SM_TOTAL>>>(out);
}